// round 1
// baseline (speedup 1.0000x reference)
#include <cuda_runtime.h>
#include <math.h>

#define LQ   256      // sequence length L
#define DHH  64       // head dim
#define NH   8        // heads
#define NM   64       // MSA rows
#define NSL  (NH*NM)  // 512 (h,m) slices
#define DMOD 512      // model dim
#define NTOK (NM*LQ)  // 16384 tokens

// ---------------- scratch (device globals; no allocation allowed) -------------
__device__ float g_q[NSL * LQ * DHH];        // [hm][i][d]
__device__ float g_k[NSL * LQ * DHH];
__device__ float g_v[NSL * LQ * DHH];
__device__ float g_e2[LQ * NSL * LQ];        // [i][hm][j]
__device__ float g_alpha[LQ * NSL * LQ];     // [i][hm][j]
__device__ float g_z1[NSL * LQ * DHH];       // [hm][i][d]
__device__ float g_z2[LQ * NH * DHH];        // [i][h][d]  (already m-reduced)

// =============================================================================
// K1: projection GEMM.  y[t][e] = sum_k X[t][k] * W[e][k]
// scatter: t=(m,i), e=(h,d)  ->  out[((h*64+m)*256 + i)*64 + d]
// tile 128(M) x 64(N) x 16(K), 256 threads, 8x4 microtile
// =============================================================================
__global__ __launch_bounds__(256) void proj_kernel(const float* __restrict__ X,
                                                   const float* __restrict__ W,
                                                   int sel)
{
    __shared__ float As[16][132];   // [k][t_row]   (transposed for fp4 reads)
    __shared__ float Bs[16][68];    // [k][e_col]

    float* outp = (sel == 0) ? g_q : ((sel == 1) ? g_k : g_v);

    const int tid = threadIdx.x;
    const int t0  = blockIdx.x * 128;
    const int e0  = blockIdx.y * 64;
    const int tr  = tid >> 4;       // 0..15  -> 8 rows each
    const int tc  = tid & 15;       // 0..15  -> 4 cols each

    float c[8][4];
#pragma unroll
    for (int u = 0; u < 8; u++)
#pragma unroll
        for (int v = 0; v < 4; v++) c[u][v] = 0.f;

    for (int k0 = 0; k0 < DMOD; k0 += 16) {
        // A: 128x16 floats = 512 float4, 2/thread; coalesced along k
#pragma unroll
        for (int l = 0; l < 2; l++) {
            int idx = tid + l * 256;          // 0..511
            int r   = idx >> 2;               // 0..127
            int k4  = idx & 3;                // 0..3
            float4 a = *(const float4*)&X[(t0 + r) * DMOD + k0 + k4 * 4];
            As[k4 * 4 + 0][r] = a.x;
            As[k4 * 4 + 1][r] = a.y;
            As[k4 * 4 + 2][r] = a.z;
            As[k4 * 4 + 3][r] = a.w;
        }
        // B: 64x16 floats = 256 float4, 1/thread
        {
            int r  = tid >> 2;                // 0..63
            int k4 = tid & 3;
            float4 b = *(const float4*)&W[(e0 + r) * DMOD + k0 + k4 * 4];
            Bs[k4 * 4 + 0][r] = b.x;
            Bs[k4 * 4 + 1][r] = b.y;
            Bs[k4 * 4 + 2][r] = b.z;
            Bs[k4 * 4 + 3][r] = b.w;
        }
        __syncthreads();
#pragma unroll
        for (int k = 0; k < 16; ++k) {
            float4 a0 = *(const float4*)&As[k][tr * 8];
            float4 a1 = *(const float4*)&As[k][tr * 8 + 4];
            float4 b  = *(const float4*)&Bs[k][tc * 4];
            float av[8] = {a0.x, a0.y, a0.z, a0.w, a1.x, a1.y, a1.z, a1.w};
            float bv[4] = {b.x, b.y, b.z, b.w};
#pragma unroll
            for (int u = 0; u < 8; u++)
#pragma unroll
                for (int v = 0; v < 4; v++) c[u][v] += av[u] * bv[v];
        }
        __syncthreads();
    }

    // epilogue scatter into [hm][i][d] layout
#pragma unroll
    for (int u = 0; u < 8; u++) {
        int t = t0 + tr * 8 + u;
        int m = t >> 8;           // token -> (m, i)
        int i = t & 255;
#pragma unroll
        for (int v = 0; v < 4; v++) {
            int e = e0 + tc * 4 + v;
            int h = e >> 6;
            int d = e & 63;
            outp[((h * NM + m) * LQ + i) * DHH + d] = c[u][v];
        }
    }
}

// =============================================================================
// K2: e2[i][hm][j] = sum_d q[hm][i][d] * aK[i][j][d]
// grid: (j_tile=4, hm_tile=8, i=256); tile 64x64, K=64
// =============================================================================
__global__ __launch_bounds__(256) void e2_kernel(const float* __restrict__ aK)
{
    __shared__ float Qs[64][68];   // [hm_r][d]
    __shared__ float Ks[64][68];   // [j_r][d]

    const int i   = blockIdx.z;
    const int hm0 = blockIdx.y * 64;
    const int j0  = blockIdx.x * 64;
    const int tid = threadIdx.x;

#pragma unroll
    for (int l = 0; l < 4; l++) {
        int idx = tid + l * 256;     // 0..1023
        int r   = idx >> 4;          // 0..63
        int d4  = idx & 15;          // 0..15
        *(float4*)&Qs[r][d4 * 4] =
            *(const float4*)&g_q[((hm0 + r) * LQ + i) * DHH + d4 * 4];
        *(float4*)&Ks[r][d4 * 4] =
            *(const float4*)&aK[(i * LQ + j0 + r) * DHH + d4 * 4];
    }
    __syncthreads();

    const int tr = tid >> 4, tc = tid & 15;
    float c[4][4];
#pragma unroll
    for (int u = 0; u < 4; u++)
#pragma unroll
        for (int v = 0; v < 4; v++) c[u][v] = 0.f;

#pragma unroll
    for (int k4 = 0; k4 < 16; k4++) {
        float4 a[4], b[4];
#pragma unroll
        for (int u = 0; u < 4; u++) {
            a[u] = *(const float4*)&Qs[tr * 4 + u][k4 * 4];
            b[u] = *(const float4*)&Ks[tc * 4 + u][k4 * 4];
        }
#pragma unroll
        for (int u = 0; u < 4; u++)
#pragma unroll
            for (int v = 0; v < 4; v++)
                c[u][v] += a[u].x * b[v].x + a[u].y * b[v].y +
                           a[u].z * b[v].z + a[u].w * b[v].w;
    }

#pragma unroll
    for (int u = 0; u < 4; u++) {
        int hm = hm0 + tr * 4 + u;
        float4 w = make_float4(c[u][0], c[u][1], c[u][2], c[u][3]);
        *(float4*)&g_e2[(i * NSL + hm) * LQ + j0 + tc * 4] = w;
    }
}

// =============================================================================
// K3: per (h,m) slice: e1 = q k^T, add e2, scale, softmax, z1 = alpha v
// one block per hm (512 blocks), one query row per thread (256 threads)
// =============================================================================
__global__ __launch_bounds__(256) void attn_kernel()
{
    __shared__ float sk[64][64];   // k (then v) tile, all-broadcast reads

    const int hm = blockIdx.x;
    const int i  = threadIdx.x;

    // q row in registers (fully unrolled)
    float q[DHH];
    const float* qp = &g_q[(hm * LQ + i) * DHH];
#pragma unroll
    for (int d = 0; d < DHH; d++) q[d] = qp[d];

    float e[LQ];   // per-row scores (local memory)

    for (int jt = 0; jt < 4; jt++) {
        __syncthreads();
#pragma unroll
        for (int l = 0; l < 4; l++) {
            int idx = threadIdx.x + l * 256;
            int r   = idx >> 4;
            int d4  = idx & 15;
            *(float4*)&sk[r][d4 * 4] =
                *(const float4*)&g_k[(hm * LQ + jt * 64 + r) * DHH + d4 * 4];
        }
        __syncthreads();
        for (int j = 0; j < 64; j++) {
            float s = 0.f;
#pragma unroll
            for (int d4 = 0; d4 < 16; d4++) {
                float4 kv = *(const float4*)&sk[j][d4 * 4];
                s += q[d4 * 4 + 0] * kv.x + q[d4 * 4 + 1] * kv.y +
                     q[d4 * 4 + 2] * kv.z + q[d4 * 4 + 3] * kv.w;
            }
            e[jt * 64 + j] = s;
        }
    }

    // add relative bias, scale, softmax
    const float* e2p = &g_e2[(i * NSL + hm) * LQ];
    float mx = -1e30f;
    for (int j4 = 0; j4 < 64; j4++) {
        float4 b = *(const float4*)&e2p[j4 * 4];
        float v0 = (e[j4 * 4 + 0] + b.x) * 0.125f;
        float v1 = (e[j4 * 4 + 1] + b.y) * 0.125f;
        float v2 = (e[j4 * 4 + 2] + b.z) * 0.125f;
        float v3 = (e[j4 * 4 + 3] + b.w) * 0.125f;
        e[j4 * 4 + 0] = v0; e[j4 * 4 + 1] = v1;
        e[j4 * 4 + 2] = v2; e[j4 * 4 + 3] = v3;
        mx = fmaxf(mx, fmaxf(fmaxf(v0, v1), fmaxf(v2, v3)));
    }
    float sum = 0.f;
    for (int j = 0; j < LQ; j++) {
        float a = __expf(e[j] - mx);
        e[j] = a;
        sum += a;
    }
    float inv = 1.f / sum;
    float* ap = &g_alpha[(i * NSL + hm) * LQ];
    for (int j4 = 0; j4 < 64; j4++) {
        float a0 = e[j4 * 4 + 0] * inv, a1 = e[j4 * 4 + 1] * inv;
        float a2 = e[j4 * 4 + 2] * inv, a3 = e[j4 * 4 + 3] * inv;
        e[j4 * 4 + 0] = a0; e[j4 * 4 + 1] = a1;
        e[j4 * 4 + 2] = a2; e[j4 * 4 + 3] = a3;
        *(float4*)&ap[j4 * 4] = make_float4(a0, a1, a2, a3);
    }

    // z1 = alpha @ v
    float acc[DHH];
#pragma unroll
    for (int d = 0; d < DHH; d++) acc[d] = 0.f;

    for (int jt = 0; jt < 4; jt++) {
        __syncthreads();
#pragma unroll
        for (int l = 0; l < 4; l++) {
            int idx = threadIdx.x + l * 256;
            int r   = idx >> 4;
            int d4  = idx & 15;
            *(float4*)&sk[r][d4 * 4] =
                *(const float4*)&g_v[(hm * LQ + jt * 64 + r) * DHH + d4 * 4];
        }
        __syncthreads();
        for (int j = 0; j < 64; j++) {
            float a = e[jt * 64 + j];
#pragma unroll
            for (int d4 = 0; d4 < 16; d4++) {
                float4 vv = *(const float4*)&sk[j][d4 * 4];
                acc[d4 * 4 + 0] += a * vv.x;
                acc[d4 * 4 + 1] += a * vv.y;
                acc[d4 * 4 + 2] += a * vv.z;
                acc[d4 * 4 + 3] += a * vv.w;
            }
        }
    }
    float* zp = &g_z1[(hm * LQ + i) * DHH];
#pragma unroll
    for (int d4 = 0; d4 < 16; d4++)
        *(float4*)&zp[d4 * 4] = make_float4(acc[d4 * 4 + 0], acc[d4 * 4 + 1],
                                            acc[d4 * 4 + 2], acc[d4 * 4 + 3]);
}

// =============================================================================
// K4: z2red[i][h][d] = sum_m sum_j alpha[i][h*64+m][j] * aV[i][j][d]
// grid (h=8, i=256); tile 64(m) x 64(d), K=256 in 4 chunks; in-block m-reduce
// =============================================================================
__global__ __launch_bounds__(256) void z2_kernel(const float* __restrict__ aV)
{
    __shared__ float As[64][68];   // [m][jj]
    __shared__ float Bs[64][68];   // [jj][d]

    const int h   = blockIdx.x;
    const int i   = blockIdx.y;
    const int tid = threadIdx.x;
    const int tr  = tid >> 4, tc = tid & 15;

    float c[4][4];
#pragma unroll
    for (int u = 0; u < 4; u++)
#pragma unroll
        for (int v = 0; v < 4; v++) c[u][v] = 0.f;

    for (int jc = 0; jc < 4; jc++) {
        __syncthreads();
#pragma unroll
        for (int l = 0; l < 4; l++) {
            int idx = tid + l * 256;
            int r   = idx >> 4;
            int q4  = idx & 15;
            *(float4*)&As[r][q4 * 4] =
                *(const float4*)&g_alpha[(i * NSL + h * NM + r) * LQ + jc * 64 + q4 * 4];
            *(float4*)&Bs[r][q4 * 4] =
                *(const float4*)&aV[(i * LQ + jc * 64 + r) * DHH + q4 * 4];
        }
        __syncthreads();
#pragma unroll 16
        for (int jj = 0; jj < 64; jj++) {
            float a[4];
#pragma unroll
            for (int u = 0; u < 4; u++) a[u] = As[tr * 4 + u][jj];
            float4 b = *(const float4*)&Bs[jj][tc * 4];
#pragma unroll
            for (int u = 0; u < 4; u++) {
                c[u][0] += a[u] * b.x;
                c[u][1] += a[u] * b.y;
                c[u][2] += a[u] * b.z;
                c[u][3] += a[u] * b.w;
            }
        }
    }

    // stage C into shared, reduce over m
    __syncthreads();
#pragma unroll
    for (int u = 0; u < 4; u++)
#pragma unroll
        for (int v = 0; v < 4; v++) As[tr * 4 + u][tc * 4 + v] = c[u][v];
    __syncthreads();

    if (tid < 64) {
        float s = 0.f;
#pragma unroll 8
        for (int m = 0; m < 64; m++) s += As[m][tid];
        g_z2[(i * NH + h) * DHH + tid] = s;
    }
}

// =============================================================================
// K5: out[i][h*64+d] = sum_m z1[h*64+m][i][d] + z2red[i][h][d]
// =============================================================================
__global__ __launch_bounds__(256) void final_kernel(float* __restrict__ out)
{
    int g    = blockIdx.x * 256 + threadIdx.x;   // 0..131071
    int i    = g >> 9;
    int rest = g & 511;
    int h    = rest >> 6;
    int d    = rest & 63;

    const float* zp = &g_z1[((h * NM) * LQ + i) * DHH + d];
    float s = g_z2[(i * NH + h) * DHH + d];
#pragma unroll 8
    for (int m = 0; m < 64; m++) s += zp[m * (LQ * DHH)];
    out[g] = s;
}

// =============================================================================
extern "C" void kernel_launch(void* const* d_in, const int* in_sizes, int n_in,
                              void* d_out, int out_size)
{
    const float* x  = (const float*)d_in[0];
    const float* Wq = (const float*)d_in[1];
    const float* Wk = (const float*)d_in[2];
    const float* Wv = (const float*)d_in[3];
    const float* aK = (const float*)d_in[4];
    const float* aV = (const float*)d_in[5];
    float* out = (float*)d_out;

    dim3 pg(NTOK / 128, DMOD / 64);        // 128 x 8
    proj_kernel<<<pg, 256>>>(x, Wq, 0);
    proj_kernel<<<pg, 256>>>(x, Wk, 1);
    proj_kernel<<<pg, 256>>>(x, Wv, 2);

    e2_kernel<<<dim3(4, 8, LQ), 256>>>(aK);

    attn_kernel<<<NSL, 256>>>();

    z2_kernel<<<dim3(NH, LQ), 256>>>(aV);

    final_kernel<<<512, 256>>>(out);
}

// round 3
// speedup vs baseline: 1.4329x; 1.4329x over previous
#include <cuda_runtime.h>
#include <cuda_bf16.h>
#include <cstdint>
#include <math.h>

#define LQ   256      // sequence length L
#define DHH  64       // head dim
#define NH   8        // heads
#define NM   64       // MSA rows
#define NSL  (NH*NM)  // 512 (h,m) slices
#define DMOD 512      // model dim
#define NTOK (NM*LQ)  // 16384 tokens

// ---------------- scratch (device globals; no allocation allowed) -------------
__device__ float g_q[NSL * LQ * DHH];        // [hm][i][d]
__device__ float g_k[NSL * LQ * DHH];
__device__ float g_v[NSL * LQ * DHH];
__device__ float g_e2[LQ * NSL * LQ];        // [i][hm][j]
__device__ float g_alpha[LQ * NSL * LQ];     // [i][hm][j]
__device__ float g_z1[NSL * LQ * DHH];       // [hm][i][d]
__device__ float g_z2[LQ * NH * DHH];        // [i][h][d]

// bf16 hi/lo splits
__device__ __nv_bfloat16 g_xhi[NTOK * DMOD];
__device__ __nv_bfloat16 g_xlo[NTOK * DMOD];
__device__ __nv_bfloat16 g_whi[3 * DMOD * DMOD];
__device__ __nv_bfloat16 g_wlo[3 * DMOD * DMOD];
__device__ __nv_bfloat16 g_qhi[NSL * LQ * DHH];   // written by proj epilogue
__device__ __nv_bfloat16 g_qlo[NSL * LQ * DHH];
__device__ __nv_bfloat16 g_akhi[LQ * LQ * DHH];
__device__ __nv_bfloat16 g_aklo[LQ * LQ * DHH];

// ========================= warp-mma helpers ==================================
__device__ __forceinline__ uint32_t smem_to_u32(const void* p) {
    uint32_t a;
    asm("{ .reg .u64 t; cvta.to.shared.u64 t, %1; cvt.u32.u64 %0, t; }"
        : "=r"(a) : "l"(p));
    return a;
}
__device__ __forceinline__ void ldsm_x4(uint32_t addr, uint32_t* r) {
    asm volatile("ldmatrix.sync.aligned.m8n8.x4.shared.b16 {%0,%1,%2,%3}, [%4];"
        : "=r"(r[0]), "=r"(r[1]), "=r"(r[2]), "=r"(r[3]) : "r"(addr));
}
__device__ __forceinline__ void mma_bf16(float* c, const uint32_t* a,
                                         const uint32_t* b) {
    asm volatile(
        "mma.sync.aligned.m16n8k16.row.col.f32.bf16.bf16.f32 "
        "{%0,%1,%2,%3}, {%4,%5,%6,%7}, {%8,%9}, {%0,%1,%2,%3};"
        : "+f"(c[0]), "+f"(c[1]), "+f"(c[2]), "+f"(c[3])
        : "r"(a[0]), "r"(a[1]), "r"(a[2]), "r"(a[3]), "r"(b[0]), "r"(b[1]));
}

#define PITCH 80                 // bytes per smem row (32 bf16 data + 16B pad)
#define SM_AHI 0
#define SM_ALO (128 * PITCH)     // 10240
#define SM_BHI (2 * 128 * PITCH) // 20480
#define SM_BLO (SM_BHI + 64 * PITCH)
#define SM_TOT (SM_BLO + 64 * PITCH)

// ============================================================================
// split kernel: fp32 -> (bf16 hi, bf16 lo)
// ============================================================================
__global__ __launch_bounds__(256) void split_kernel(const float* __restrict__ src,
                                                    __nv_bfloat16* __restrict__ hi,
                                                    __nv_bfloat16* __restrict__ lo,
                                                    int nvec)
{
    int idx = blockIdx.x * 256 + threadIdx.x;
    if (idx >= nvec) return;
    float4 v = *(const float4*)&src[idx * 4];
    __nv_bfloat16 h0 = __float2bfloat16(v.x);
    __nv_bfloat16 h1 = __float2bfloat16(v.y);
    __nv_bfloat16 h2 = __float2bfloat16(v.z);
    __nv_bfloat16 h3 = __float2bfloat16(v.w);
    __nv_bfloat162 hp0(h0, h1), hp1(h2, h3);
    __nv_bfloat162 lp0(__float2bfloat16(v.x - __bfloat162float(h0)),
                       __float2bfloat16(v.y - __bfloat162float(h1)));
    __nv_bfloat162 lp1(__float2bfloat16(v.z - __bfloat162float(h2)),
                       __float2bfloat16(v.w - __bfloat162float(h3)));
    *(__nv_bfloat162*)&hi[idx * 4]     = hp0;
    *(__nv_bfloat162*)&hi[idx * 4 + 2] = hp1;
    *(__nv_bfloat162*)&lo[idx * 4]     = lp0;
    *(__nv_bfloat162*)&lo[idx * 4 + 2] = lp1;
}

// ============================================================================
// K1: projection GEMM via mma.sync bf16-split.
// C[t][e] = sum_k X[t][k] * W[e][k];  CTA 128(M) x 64(N), K=512 in 16 chunks.
// 8 warps (4m x 2n), warp tile 32x32.
// ============================================================================
__global__ __launch_bounds__(256) void proj_mma_kernel()
{
    __shared__ __align__(16) unsigned char sm[SM_TOT];
    const uint32_t sb = smem_to_u32(sm);

    const int tid  = threadIdx.x;
    const int lane = tid & 31;
    const int wid  = tid >> 5;
    const int t0   = blockIdx.x * 128;
    const int n0   = blockIdx.y * 64;
    const int sel  = blockIdx.z;

    const __nv_bfloat16* Ah = g_xhi;
    const __nv_bfloat16* Al = g_xlo;
    const __nv_bfloat16* Bh = g_whi + sel * DMOD * DMOD;
    const __nv_bfloat16* Bl = g_wlo + sel * DMOD * DMOD;
    float* outp = (sel == 0) ? g_q : ((sel == 1) ? g_k : g_v);

    const int wm = (wid & 3) * 32;
    const int wn = (wid >> 2) * 32;

    float acc[2][4][4];
#pragma unroll
    for (int a = 0; a < 2; a++)
#pragma unroll
        for (int b = 0; b < 4; b++)
#pragma unroll
            for (int c = 0; c < 4; c++) acc[a][b][c] = 0.f;

    for (int ch = 0; ch < 16; ch++) {
        const int k0 = ch * 32;
#pragma unroll
        for (int l = 0; l < 2; l++) {
            int id = tid + l * 256;
            int r = id >> 2, cc = id & 3;
            *(float4*)(sm + SM_AHI + r * PITCH + cc * 16) =
                *(const float4*)&Ah[(t0 + r) * DMOD + k0 + cc * 8];
            *(float4*)(sm + SM_ALO + r * PITCH + cc * 16) =
                *(const float4*)&Al[(t0 + r) * DMOD + k0 + cc * 8];
        }
        {
            int r = tid >> 2, cc = tid & 3;
            *(float4*)(sm + SM_BHI + r * PITCH + cc * 16) =
                *(const float4*)&Bh[(n0 + r) * DMOD + k0 + cc * 8];
            *(float4*)(sm + SM_BLO + r * PITCH + cc * 16) =
                *(const float4*)&Bl[(n0 + r) * DMOD + k0 + cc * 8];
        }
        __syncthreads();

#pragma unroll
        for (int s = 0; s < 2; s++) {
            uint32_t ah[2][4], al[2][4], bh[2][4], bl[2][4];
#pragma unroll
            for (int mi = 0; mi < 2; mi++) {
                int row = wm + mi * 16 + (lane & 7) + ((lane >> 3) & 1) * 8;
                uint32_t ad = sb + row * PITCH + s * 32 + ((lane >> 4) & 1) * 16;
                ldsm_x4(ad + SM_AHI, ah[mi]);
                ldsm_x4(ad + SM_ALO, al[mi]);
            }
#pragma unroll
            for (int p = 0; p < 2; p++) {
                int row = wn + p * 16 + (lane & 7) + ((lane >> 4) & 1) * 8;
                uint32_t bd = sb + row * PITCH + s * 32 + ((lane >> 3) & 1) * 16;
                ldsm_x4(bd + SM_BHI, bh[p]);
                ldsm_x4(bd + SM_BLO, bl[p]);
            }
#pragma unroll
            for (int mi = 0; mi < 2; mi++)
#pragma unroll
                for (int p = 0; p < 2; p++)
#pragma unroll
                    for (int su = 0; su < 2; su++) {
                        int ni = p * 2 + su;
                        mma_bf16(acc[mi][ni], ah[mi], &bh[p][su * 2]);
                        mma_bf16(acc[mi][ni], ah[mi], &bl[p][su * 2]);
                        mma_bf16(acc[mi][ni], al[mi], &bh[p][su * 2]);
                    }
        }
        __syncthreads();
    }

    // epilogue: scatter to [hm][i][d]; for q also emit bf16 hi/lo
#pragma unroll
    for (int mi = 0; mi < 2; mi++)
#pragma unroll
        for (int ni = 0; ni < 4; ni++) {
            int e = n0 + wn + ni * 8 + (lane & 3) * 2;
            int h = e >> 6, d = e & 63;
#pragma unroll
            for (int rr = 0; rr < 2; rr++) {
                int t = t0 + wm + mi * 16 + (lane >> 2) + rr * 8;
                int m = t >> 8, i = t & 255;
                int idx = ((h * NM + m) * LQ + i) * DHH + d;
                float vx = acc[mi][ni][rr * 2 + 0];
                float vy = acc[mi][ni][rr * 2 + 1];
                *(float2*)&outp[idx] = make_float2(vx, vy);
                if (sel == 0) {
                    __nv_bfloat16 h0 = __float2bfloat16(vx);
                    __nv_bfloat16 h1 = __float2bfloat16(vy);
                    __nv_bfloat162 hp(h0, h1);
                    __nv_bfloat162 lp(__float2bfloat16(vx - __bfloat162float(h0)),
                                      __float2bfloat16(vy - __bfloat162float(h1)));
                    *(__nv_bfloat162*)&g_qhi[idx] = hp;
                    *(__nv_bfloat162*)&g_qlo[idx] = lp;
                }
            }
        }
}

// ============================================================================
// K2: e2[i][hm][j] = sum_d q[hm][i][d] * aK[i][j][d]  via mma.sync bf16-split
// CTA 128(hm) x 64(j), K=64 in 2 chunks; grid (4, 4, 256)
// ============================================================================
__global__ __launch_bounds__(256) void e2_mma_kernel()
{
    __shared__ __align__(16) unsigned char sm[SM_TOT];
    const uint32_t sb = smem_to_u32(sm);

    const int tid  = threadIdx.x;
    const int lane = tid & 31;
    const int wid  = tid >> 5;
    const int hm0  = blockIdx.x * 128;
    const int j0   = blockIdx.y * 64;
    const int i    = blockIdx.z;

    const int wm = (wid & 3) * 32;
    const int wn = (wid >> 2) * 32;

    float acc[2][4][4];
#pragma unroll
    for (int a = 0; a < 2; a++)
#pragma unroll
        for (int b = 0; b < 4; b++)
#pragma unroll
            for (int c = 0; c < 4; c++) acc[a][b][c] = 0.f;

    for (int ch = 0; ch < 2; ch++) {
        const int k0 = ch * 32;
#pragma unroll
        for (int l = 0; l < 2; l++) {
            int id = tid + l * 256;
            int r = id >> 2, cc = id & 3;
            int ga = ((hm0 + r) * LQ + i) * DHH + k0 + cc * 8;
            *(float4*)(sm + SM_AHI + r * PITCH + cc * 16) = *(const float4*)&g_qhi[ga];
            *(float4*)(sm + SM_ALO + r * PITCH + cc * 16) = *(const float4*)&g_qlo[ga];
        }
        {
            int r = tid >> 2, cc = tid & 3;
            int gb = (i * LQ + j0 + r) * DHH + k0 + cc * 8;
            *(float4*)(sm + SM_BHI + r * PITCH + cc * 16) = *(const float4*)&g_akhi[gb];
            *(float4*)(sm + SM_BLO + r * PITCH + cc * 16) = *(const float4*)&g_aklo[gb];
        }
        __syncthreads();

#pragma unroll
        for (int s = 0; s < 2; s++) {
            uint32_t ah[2][4], al[2][4], bh[2][4], bl[2][4];
#pragma unroll
            for (int mi = 0; mi < 2; mi++) {
                int row = wm + mi * 16 + (lane & 7) + ((lane >> 3) & 1) * 8;
                uint32_t ad = sb + row * PITCH + s * 32 + ((lane >> 4) & 1) * 16;
                ldsm_x4(ad + SM_AHI, ah[mi]);
                ldsm_x4(ad + SM_ALO, al[mi]);
            }
#pragma unroll
            for (int p = 0; p < 2; p++) {
                int row = wn + p * 16 + (lane & 7) + ((lane >> 4) & 1) * 8;
                uint32_t bd = sb + row * PITCH + s * 32 + ((lane >> 3) & 1) * 16;
                ldsm_x4(bd + SM_BHI, bh[p]);
                ldsm_x4(bd + SM_BLO, bl[p]);
            }
#pragma unroll
            for (int mi = 0; mi < 2; mi++)
#pragma unroll
                for (int p = 0; p < 2; p++)
#pragma unroll
                    for (int su = 0; su < 2; su++) {
                        int ni = p * 2 + su;
                        mma_bf16(acc[mi][ni], ah[mi], &bh[p][su * 2]);
                        mma_bf16(acc[mi][ni], ah[mi], &bl[p][su * 2]);
                        mma_bf16(acc[mi][ni], al[mi], &bh[p][su * 2]);
                    }
        }
        __syncthreads();
    }

#pragma unroll
    for (int mi = 0; mi < 2; mi++)
#pragma unroll
        for (int ni = 0; ni < 4; ni++) {
            int j = j0 + wn + ni * 8 + (lane & 3) * 2;
#pragma unroll
            for (int rr = 0; rr < 2; rr++) {
                int hm = hm0 + wm + mi * 16 + (lane >> 2) + rr * 8;
                *(float2*)&g_e2[(i * NSL + hm) * LQ + j] =
                    make_float2(acc[mi][ni][rr * 2 + 0], acc[mi][ni][rr * 2 + 1]);
            }
        }
}

// =============================================================================
// K3: per (h,m): e1 = q k^T, + e2, scale, softmax, z1 = alpha v
// =============================================================================
__global__ __launch_bounds__(256) void attn_kernel()
{
    __shared__ float sk[64][64];

    const int hm = blockIdx.x;
    const int i  = threadIdx.x;

    float q[DHH];
    const float* qp = &g_q[(hm * LQ + i) * DHH];
#pragma unroll
    for (int d = 0; d < DHH; d++) q[d] = qp[d];

    float e[LQ];

    for (int jt = 0; jt < 4; jt++) {
        __syncthreads();
#pragma unroll
        for (int l = 0; l < 4; l++) {
            int idx = threadIdx.x + l * 256;
            int r   = idx >> 4;
            int d4  = idx & 15;
            *(float4*)&sk[r][d4 * 4] =
                *(const float4*)&g_k[(hm * LQ + jt * 64 + r) * DHH + d4 * 4];
        }
        __syncthreads();
        for (int j = 0; j < 64; j++) {
            float s = 0.f;
#pragma unroll
            for (int d4 = 0; d4 < 16; d4++) {
                float4 kv = *(const float4*)&sk[j][d4 * 4];
                s += q[d4 * 4 + 0] * kv.x + q[d4 * 4 + 1] * kv.y +
                     q[d4 * 4 + 2] * kv.z + q[d4 * 4 + 3] * kv.w;
            }
            e[jt * 64 + j] = s;
        }
    }

    const float* e2p = &g_e2[(i * NSL + hm) * LQ];
    float mx = -1e30f;
    for (int j4 = 0; j4 < 64; j4++) {
        float4 b = *(const float4*)&e2p[j4 * 4];
        float v0 = (e[j4 * 4 + 0] + b.x) * 0.125f;
        float v1 = (e[j4 * 4 + 1] + b.y) * 0.125f;
        float v2 = (e[j4 * 4 + 2] + b.z) * 0.125f;
        float v3 = (e[j4 * 4 + 3] + b.w) * 0.125f;
        e[j4 * 4 + 0] = v0; e[j4 * 4 + 1] = v1;
        e[j4 * 4 + 2] = v2; e[j4 * 4 + 3] = v3;
        mx = fmaxf(mx, fmaxf(fmaxf(v0, v1), fmaxf(v2, v3)));
    }
    float sum = 0.f;
    for (int j = 0; j < LQ; j++) {
        float a = __expf(e[j] - mx);
        e[j] = a;
        sum += a;
    }
    float inv = 1.f / sum;
    float* ap = &g_alpha[(i * NSL + hm) * LQ];
    for (int j4 = 0; j4 < 64; j4++) {
        float a0 = e[j4 * 4 + 0] * inv, a1 = e[j4 * 4 + 1] * inv;
        float a2 = e[j4 * 4 + 2] * inv, a3 = e[j4 * 4 + 3] * inv;
        e[j4 * 4 + 0] = a0; e[j4 * 4 + 1] = a1;
        e[j4 * 4 + 2] = a2; e[j4 * 4 + 3] = a3;
        *(float4*)&ap[j4 * 4] = make_float4(a0, a1, a2, a3);
    }

    float acc[DHH];
#pragma unroll
    for (int d = 0; d < DHH; d++) acc[d] = 0.f;

    for (int jt = 0; jt < 4; jt++) {
        __syncthreads();
#pragma unroll
        for (int l = 0; l < 4; l++) {
            int idx = threadIdx.x + l * 256;
            int r   = idx >> 4;
            int d4  = idx & 15;
            *(float4*)&sk[r][d4 * 4] =
                *(const float4*)&g_v[(hm * LQ + jt * 64 + r) * DHH + d4 * 4];
        }
        __syncthreads();
        for (int j = 0; j < 64; j++) {
            float a = e[jt * 64 + j];
#pragma unroll
            for (int d4 = 0; d4 < 16; d4++) {
                float4 vv = *(const float4*)&sk[j][d4 * 4];
                acc[d4 * 4 + 0] += a * vv.x;
                acc[d4 * 4 + 1] += a * vv.y;
                acc[d4 * 4 + 2] += a * vv.z;
                acc[d4 * 4 + 3] += a * vv.w;
            }
        }
    }
    float* zp = &g_z1[(hm * LQ + i) * DHH];
#pragma unroll
    for (int d4 = 0; d4 < 16; d4++)
        *(float4*)&zp[d4 * 4] = make_float4(acc[d4 * 4 + 0], acc[d4 * 4 + 1],
                                            acc[d4 * 4 + 2], acc[d4 * 4 + 3]);
}

// =============================================================================
// K4: z2[i][h][d] = sum_m sum_j alpha[i][h*64+m][j] * aV[i][j][d]
// =============================================================================
__global__ __launch_bounds__(256) void z2_kernel(const float* __restrict__ aV)
{
    __shared__ float As[64][68];
    __shared__ float Bs[64][68];

    const int h   = blockIdx.x;
    const int i   = blockIdx.y;
    const int tid = threadIdx.x;
    const int tr  = tid >> 4, tc = tid & 15;

    float c[4][4];
#pragma unroll
    for (int u = 0; u < 4; u++)
#pragma unroll
        for (int v = 0; v < 4; v++) c[u][v] = 0.f;

    for (int jc = 0; jc < 4; jc++) {
        __syncthreads();
#pragma unroll
        for (int l = 0; l < 4; l++) {
            int idx = tid + l * 256;
            int r   = idx >> 4;
            int q4  = idx & 15;
            *(float4*)&As[r][q4 * 4] =
                *(const float4*)&g_alpha[(i * NSL + h * NM + r) * LQ + jc * 64 + q4 * 4];
            *(float4*)&Bs[r][q4 * 4] =
                *(const float4*)&aV[(i * LQ + jc * 64 + r) * DHH + q4 * 4];
        }
        __syncthreads();
#pragma unroll 16
        for (int jj = 0; jj < 64; jj++) {
            float a[4];
#pragma unroll
            for (int u = 0; u < 4; u++) a[u] = As[tr * 4 + u][jj];
            float4 b = *(const float4*)&Bs[jj][tc * 4];
#pragma unroll
            for (int u = 0; u < 4; u++) {
                c[u][0] += a[u] * b.x;
                c[u][1] += a[u] * b.y;
                c[u][2] += a[u] * b.z;
                c[u][3] += a[u] * b.w;
            }
        }
    }

    __syncthreads();
#pragma unroll
    for (int u = 0; u < 4; u++)
#pragma unroll
        for (int v = 0; v < 4; v++) As[tr * 4 + u][tc * 4 + v] = c[u][v];
    __syncthreads();

    if (tid < 64) {
        float s = 0.f;
#pragma unroll 8
        for (int m = 0; m < 64; m++) s += As[m][tid];
        g_z2[(i * NH + h) * DHH + tid] = s;
    }
}

// =============================================================================
// K5: out[i][h*64+d] = sum_m z1[h*64+m][i][d] + z2[i][h][d]
// =============================================================================
__global__ __launch_bounds__(256) void final_kernel(float* __restrict__ out)
{
    int g    = blockIdx.x * 256 + threadIdx.x;
    int i    = g >> 9;
    int rest = g & 511;
    int h    = rest >> 6;
    int d    = rest & 63;

    const float* zp = &g_z1[((h * NM) * LQ + i) * DHH + d];
    float s = g_z2[(i * NH + h) * DHH + d];
#pragma unroll 8
    for (int m = 0; m < 64; m++) s += zp[m * (LQ * DHH)];
    out[g] = s;
}

// =============================================================================
extern "C" void kernel_launch(void* const* d_in, const int* in_sizes, int n_in,
                              void* d_out, int out_size)
{
    const float* x  = (const float*)d_in[0];
    const float* Wq = (const float*)d_in[1];
    const float* Wk = (const float*)d_in[2];
    const float* Wv = (const float*)d_in[3];
    const float* aK = (const float*)d_in[4];
    const float* aV = (const float*)d_in[5];
    float* out = (float*)d_out;

    __nv_bfloat16 *xhi_p, *xlo_p, *whi_p, *wlo_p, *akhi_p, *aklo_p;
    cudaGetSymbolAddress((void**)&xhi_p,  g_xhi);
    cudaGetSymbolAddress((void**)&xlo_p,  g_xlo);
    cudaGetSymbolAddress((void**)&whi_p,  g_whi);
    cudaGetSymbolAddress((void**)&wlo_p,  g_wlo);
    cudaGetSymbolAddress((void**)&akhi_p, g_akhi);
    cudaGetSymbolAddress((void**)&aklo_p, g_aklo);

    split_kernel<<<(NTOK * DMOD / 4) / 256, 256>>>(x, xhi_p, xlo_p, NTOK * DMOD / 4);
    split_kernel<<<(DMOD * DMOD / 4) / 256, 256>>>(Wq, whi_p, wlo_p, DMOD * DMOD / 4);
    split_kernel<<<(DMOD * DMOD / 4) / 256, 256>>>(Wk, whi_p + DMOD * DMOD,
                                                   wlo_p + DMOD * DMOD, DMOD * DMOD / 4);
    split_kernel<<<(DMOD * DMOD / 4) / 256, 256>>>(Wv, whi_p + 2 * DMOD * DMOD,
                                                   wlo_p + 2 * DMOD * DMOD, DMOD * DMOD / 4);
    split_kernel<<<(LQ * LQ * DHH / 4) / 256, 256>>>(aK, akhi_p, aklo_p, LQ * LQ * DHH / 4);

    proj_mma_kernel<<<dim3(NTOK / 128, DMOD / 64, 3), 256>>>();
    e2_mma_kernel<<<dim3(4, 4, LQ), 256>>>();
    attn_kernel<<<NSL, 256>>>();
    z2_kernel<<<dim3(NH, LQ), 256>>>(aV);
    final_kernel<<<512, 256>>>(out);
}

// round 4
// speedup vs baseline: 1.8489x; 1.2903x over previous
#include <cuda_runtime.h>
#include <cuda_bf16.h>
#include <cstdint>
#include <math.h>

#define LQ   256      // sequence length L
#define DHH  64       // head dim
#define NH   8        // heads
#define NM   64       // MSA rows
#define NSL  (NH*NM)  // 512 (h,m) slices
#define DMOD 512      // model dim
#define NTOK (NM*LQ)  // 16384 tokens

// ---------------- scratch (device globals; no allocation allowed) -------------
__device__ float g_e2[LQ * NSL * LQ];        // [i][hm][j]
__device__ float g_z1[NSL * LQ * DHH];       // [hm][i][d]
__device__ float g_z2[LQ * NH * DHH];        // [i][h][d]

// bf16 hi/lo splits
__device__ __nv_bfloat16 g_xhi[NTOK * DMOD];
__device__ __nv_bfloat16 g_xlo[NTOK * DMOD];
__device__ __nv_bfloat16 g_whi[3 * DMOD * DMOD];
__device__ __nv_bfloat16 g_wlo[3 * DMOD * DMOD];
__device__ __nv_bfloat16 g_qhi[NSL * LQ * DHH];   // [hm][i][d]
__device__ __nv_bfloat16 g_qlo[NSL * LQ * DHH];
__device__ __nv_bfloat16 g_khi[NSL * LQ * DHH];
__device__ __nv_bfloat16 g_klo[NSL * LQ * DHH];
__device__ __nv_bfloat16 g_vhi[NSL * LQ * DHH];
__device__ __nv_bfloat16 g_vlo[NSL * LQ * DHH];
__device__ __nv_bfloat16 g_akhi[LQ * LQ * DHH];
__device__ __nv_bfloat16 g_aklo[LQ * LQ * DHH];
__device__ __nv_bfloat16 g_avhi[LQ * LQ * DHH];
__device__ __nv_bfloat16 g_avlo[LQ * LQ * DHH];
__device__ __nv_bfloat16 g_ahi[LQ * NSL * LQ];    // alpha hi [i][hm][j]
__device__ __nv_bfloat16 g_alo[LQ * NSL * LQ];

// ========================= warp-mma helpers ==================================
__device__ __forceinline__ uint32_t smem_to_u32(const void* p) {
    uint32_t a;
    asm("{ .reg .u64 t; cvta.to.shared.u64 t, %1; cvt.u32.u64 %0, t; }"
        : "=r"(a) : "l"(p));
    return a;
}
__device__ __forceinline__ void ldsm_x4(uint32_t addr, uint32_t* r) {
    asm volatile("ldmatrix.sync.aligned.m8n8.x4.shared.b16 {%0,%1,%2,%3}, [%4];"
        : "=r"(r[0]), "=r"(r[1]), "=r"(r[2]), "=r"(r[3]) : "r"(addr));
}
__device__ __forceinline__ void ldsm_x4_t(uint32_t addr, uint32_t* r) {
    asm volatile("ldmatrix.sync.aligned.m8n8.x4.trans.shared.b16 {%0,%1,%2,%3}, [%4];"
        : "=r"(r[0]), "=r"(r[1]), "=r"(r[2]), "=r"(r[3]) : "r"(addr));
}
__device__ __forceinline__ void mma_bf16(float* c, const uint32_t* a,
                                         const uint32_t* b) {
    asm volatile(
        "mma.sync.aligned.m16n8k16.row.col.f32.bf16.bf16.f32 "
        "{%0,%1,%2,%3}, {%4,%5,%6,%7}, {%8,%9}, {%0,%1,%2,%3};"
        : "+f"(c[0]), "+f"(c[1]), "+f"(c[2]), "+f"(c[3])
        : "r"(a[0]), "r"(a[1]), "r"(a[2]), "r"(a[3]), "r"(b[0]), "r"(b[1]));
}

#define PITCH 80                 // proj/e2 smem row pitch
#define SM_AHI 0
#define SM_ALO (128 * PITCH)
#define SM_BHI (2 * 128 * PITCH)
#define SM_BLO (SM_BHI + 64 * PITCH)
#define SM_TOT (SM_BLO + 64 * PITCH)

// ============================================================================
// split: fp32 -> (bf16 hi, bf16 lo)
// ============================================================================
__global__ __launch_bounds__(256) void split_kernel(const float* __restrict__ src,
                                                    __nv_bfloat16* __restrict__ hi,
                                                    __nv_bfloat16* __restrict__ lo,
                                                    int nvec)
{
    int idx = blockIdx.x * 256 + threadIdx.x;
    if (idx >= nvec) return;
    float4 v = *(const float4*)&src[idx * 4];
    __nv_bfloat16 h0 = __float2bfloat16(v.x);
    __nv_bfloat16 h1 = __float2bfloat16(v.y);
    __nv_bfloat16 h2 = __float2bfloat16(v.z);
    __nv_bfloat16 h3 = __float2bfloat16(v.w);
    __nv_bfloat162 hp0(h0, h1), hp1(h2, h3);
    __nv_bfloat162 lp0(__float2bfloat16(v.x - __bfloat162float(h0)),
                       __float2bfloat16(v.y - __bfloat162float(h1)));
    __nv_bfloat162 lp1(__float2bfloat16(v.z - __bfloat162float(h2)),
                       __float2bfloat16(v.w - __bfloat162float(h3)));
    *(__nv_bfloat162*)&hi[idx * 4]     = hp0;
    *(__nv_bfloat162*)&hi[idx * 4 + 2] = hp1;
    *(__nv_bfloat162*)&lo[idx * 4]     = lp0;
    *(__nv_bfloat162*)&lo[idx * 4 + 2] = lp1;
}

// ============================================================================
// K1: projection GEMM (mma.sync bf16-split), outputs bf16 hi/lo only
// ============================================================================
__global__ __launch_bounds__(256) void proj_mma_kernel()
{
    __shared__ __align__(16) unsigned char sm[SM_TOT];
    const uint32_t sb = smem_to_u32(sm);

    const int tid = threadIdx.x;
    const int lane = tid & 31;
    const int wid = tid >> 5;
    const int t0 = blockIdx.x * 128;
    const int n0 = blockIdx.y * 64;
    const int sel = blockIdx.z;

    const __nv_bfloat16* Ah = g_xhi;
    const __nv_bfloat16* Al = g_xlo;
    const __nv_bfloat16* Bh = g_whi + sel * DMOD * DMOD;
    const __nv_bfloat16* Bl = g_wlo + sel * DMOD * DMOD;
    __nv_bfloat16 *hip, *lop;
    if (sel == 0)      { hip = g_qhi; lop = g_qlo; }
    else if (sel == 1) { hip = g_khi; lop = g_klo; }
    else               { hip = g_vhi; lop = g_vlo; }

    const int wm = (wid & 3) * 32;
    const int wn = (wid >> 2) * 32;

    float acc[2][4][4];
#pragma unroll
    for (int a = 0; a < 2; a++)
#pragma unroll
        for (int b = 0; b < 4; b++)
#pragma unroll
            for (int c = 0; c < 4; c++) acc[a][b][c] = 0.f;

    for (int ch = 0; ch < 16; ch++) {
        const int k0 = ch * 32;
#pragma unroll
        for (int l = 0; l < 2; l++) {
            int id = tid + l * 256;
            int r = id >> 2, cc = id & 3;
            *(float4*)(sm + SM_AHI + r * PITCH + cc * 16) =
                *(const float4*)&Ah[(t0 + r) * DMOD + k0 + cc * 8];
            *(float4*)(sm + SM_ALO + r * PITCH + cc * 16) =
                *(const float4*)&Al[(t0 + r) * DMOD + k0 + cc * 8];
        }
        {
            int r = tid >> 2, cc = tid & 3;
            *(float4*)(sm + SM_BHI + r * PITCH + cc * 16) =
                *(const float4*)&Bh[(n0 + r) * DMOD + k0 + cc * 8];
            *(float4*)(sm + SM_BLO + r * PITCH + cc * 16) =
                *(const float4*)&Bl[(n0 + r) * DMOD + k0 + cc * 8];
        }
        __syncthreads();

#pragma unroll
        for (int s = 0; s < 2; s++) {
            uint32_t ah[2][4], al[2][4], bh[2][4], bl[2][4];
#pragma unroll
            for (int mi = 0; mi < 2; mi++) {
                int row = wm + mi * 16 + (lane & 15);
                uint32_t ad = sb + row * PITCH + s * 32 + ((lane >> 4) & 1) * 16;
                ldsm_x4(ad + SM_AHI, ah[mi]);
                ldsm_x4(ad + SM_ALO, al[mi]);
            }
#pragma unroll
            for (int p = 0; p < 2; p++) {
                int row = wn + p * 16 + (lane & 7) + ((lane >> 4) & 1) * 8;
                uint32_t bd = sb + row * PITCH + s * 32 + ((lane >> 3) & 1) * 16;
                ldsm_x4(bd + SM_BHI, bh[p]);
                ldsm_x4(bd + SM_BLO, bl[p]);
            }
#pragma unroll
            for (int mi = 0; mi < 2; mi++)
#pragma unroll
                for (int p = 0; p < 2; p++)
#pragma unroll
                    for (int su = 0; su < 2; su++) {
                        int ni = p * 2 + su;
                        mma_bf16(acc[mi][ni], ah[mi], &bh[p][su * 2]);
                        mma_bf16(acc[mi][ni], ah[mi], &bl[p][su * 2]);
                        mma_bf16(acc[mi][ni], al[mi], &bh[p][su * 2]);
                    }
        }
        __syncthreads();
    }

#pragma unroll
    for (int mi = 0; mi < 2; mi++)
#pragma unroll
        for (int ni = 0; ni < 4; ni++) {
            int e = n0 + wn + ni * 8 + (lane & 3) * 2;
            int h = e >> 6, d = e & 63;
#pragma unroll
            for (int rr = 0; rr < 2; rr++) {
                int t = t0 + wm + mi * 16 + (lane >> 2) + rr * 8;
                int m = t >> 8, i = t & 255;
                int idx = ((h * NM + m) * LQ + i) * DHH + d;
                float vx = acc[mi][ni][rr * 2 + 0];
                float vy = acc[mi][ni][rr * 2 + 1];
                __nv_bfloat16 h0 = __float2bfloat16(vx);
                __nv_bfloat16 h1 = __float2bfloat16(vy);
                __nv_bfloat162 hp(h0, h1);
                __nv_bfloat162 lp(__float2bfloat16(vx - __bfloat162float(h0)),
                                  __float2bfloat16(vy - __bfloat162float(h1)));
                *(__nv_bfloat162*)&hip[idx] = hp;
                *(__nv_bfloat162*)&lop[idx] = lp;
            }
        }
}

// ============================================================================
// K2: e2[i][hm][j] = sum_d q[hm][i][d] * aK[i][j][d]  (mma.sync bf16-split)
// ============================================================================
__global__ __launch_bounds__(256) void e2_mma_kernel()
{
    __shared__ __align__(16) unsigned char sm[SM_TOT];
    const uint32_t sb = smem_to_u32(sm);

    const int tid = threadIdx.x;
    const int lane = tid & 31;
    const int wid = tid >> 5;
    const int hm0 = blockIdx.x * 128;
    const int j0 = blockIdx.y * 64;
    const int i = blockIdx.z;

    const int wm = (wid & 3) * 32;
    const int wn = (wid >> 2) * 32;

    float acc[2][4][4];
#pragma unroll
    for (int a = 0; a < 2; a++)
#pragma unroll
        for (int b = 0; b < 4; b++)
#pragma unroll
            for (int c = 0; c < 4; c++) acc[a][b][c] = 0.f;

    for (int ch = 0; ch < 2; ch++) {
        const int k0 = ch * 32;
#pragma unroll
        for (int l = 0; l < 2; l++) {
            int id = tid + l * 256;
            int r = id >> 2, cc = id & 3;
            int ga = ((hm0 + r) * LQ + i) * DHH + k0 + cc * 8;
            *(float4*)(sm + SM_AHI + r * PITCH + cc * 16) = *(const float4*)&g_qhi[ga];
            *(float4*)(sm + SM_ALO + r * PITCH + cc * 16) = *(const float4*)&g_qlo[ga];
        }
        {
            int r = tid >> 2, cc = tid & 3;
            int gb = (i * LQ + j0 + r) * DHH + k0 + cc * 8;
            *(float4*)(sm + SM_BHI + r * PITCH + cc * 16) = *(const float4*)&g_akhi[gb];
            *(float4*)(sm + SM_BLO + r * PITCH + cc * 16) = *(const float4*)&g_aklo[gb];
        }
        __syncthreads();

#pragma unroll
        for (int s = 0; s < 2; s++) {
            uint32_t ah[2][4], al[2][4], bh[2][4], bl[2][4];
#pragma unroll
            for (int mi = 0; mi < 2; mi++) {
                int row = wm + mi * 16 + (lane & 15);
                uint32_t ad = sb + row * PITCH + s * 32 + ((lane >> 4) & 1) * 16;
                ldsm_x4(ad + SM_AHI, ah[mi]);
                ldsm_x4(ad + SM_ALO, al[mi]);
            }
#pragma unroll
            for (int p = 0; p < 2; p++) {
                int row = wn + p * 16 + (lane & 7) + ((lane >> 4) & 1) * 8;
                uint32_t bd = sb + row * PITCH + s * 32 + ((lane >> 3) & 1) * 16;
                ldsm_x4(bd + SM_BHI, bh[p]);
                ldsm_x4(bd + SM_BLO, bl[p]);
            }
#pragma unroll
            for (int mi = 0; mi < 2; mi++)
#pragma unroll
                for (int p = 0; p < 2; p++)
#pragma unroll
                    for (int su = 0; su < 2; su++) {
                        int ni = p * 2 + su;
                        mma_bf16(acc[mi][ni], ah[mi], &bh[p][su * 2]);
                        mma_bf16(acc[mi][ni], ah[mi], &bl[p][su * 2]);
                        mma_bf16(acc[mi][ni], al[mi], &bh[p][su * 2]);
                    }
        }
        __syncthreads();
    }

#pragma unroll
    for (int mi = 0; mi < 2; mi++)
#pragma unroll
        for (int ni = 0; ni < 4; ni++) {
            int j = j0 + wn + ni * 8 + (lane & 3) * 2;
#pragma unroll
            for (int rr = 0; rr < 2; rr++) {
                int hm = hm0 + wm + mi * 16 + (lane >> 2) + rr * 8;
                *(float2*)&g_e2[(i * NSL + hm) * LQ + j] =
                    make_float2(acc[mi][ni][rr * 2 + 0], acc[mi][ni][rr * 2 + 1]);
            }
        }
}

// ============================================================================
// K3: attn per hm: e1 (mma) + e2 + softmax + z1 (mma), alpha -> bf16 hi/lo
// smem: Q[256x144]x2 | KV[64x144]x2 | S fp32[256x65]; alpha reuses Q region
// ============================================================================
#define AT_Q    0
#define AT_QSZ  (256 * 144)            // 36864
#define AT_KV   (2 * AT_QSZ)           // 73728
#define AT_KVSZ (64 * 144)             // 9216
#define AT_S    (AT_KV + 2 * AT_KVSZ)  // 92160
#define AT_TOT  (AT_S + 256 * 65 * 4)  // 158720

__global__ __launch_bounds__(256) void attn_mma_kernel()
{
    extern __shared__ __align__(16) unsigned char dsm[];
    const uint32_t sb = smem_to_u32(dsm);
    const int tid = threadIdx.x, lane = tid & 31, wid = tid >> 5;
    const int hm = blockIdx.x;
    const int wm = wid * 32;
    float* Sf = (float*)(dsm + AT_S);

    // load Q hi/lo (resident for phase 1)
    {
        const __nv_bfloat16* qh = &g_qhi[hm * LQ * DHH];
        const __nv_bfloat16* ql = &g_qlo[hm * LQ * DHH];
#pragma unroll
        for (int l = 0; l < 8; l++) {
            int id = tid + l * 256;
            int r = id >> 3, c = id & 7;
            *(float4*)(dsm + AT_Q + r * 144 + c * 16) =
                *(const float4*)&qh[r * 64 + c * 8];
            *(float4*)(dsm + AT_Q + AT_QSZ + r * 144 + c * 16) =
                *(const float4*)&ql[r * 64 + c * 8];
        }
    }

    float e[LQ];

    // ---------------- phase 1: e1 = q k^T per 64-j chunk ----------------
    for (int jc = 0; jc < 4; jc++) {
        __syncthreads();
        {
            const __nv_bfloat16* kh = &g_khi[(hm * LQ + jc * 64) * DHH];
            const __nv_bfloat16* kl = &g_klo[(hm * LQ + jc * 64) * DHH];
#pragma unroll
            for (int l = 0; l < 2; l++) {
                int id = tid + l * 256;
                int r = id >> 3, c = id & 7;
                *(float4*)(dsm + AT_KV + r * 144 + c * 16) =
                    *(const float4*)&kh[r * 64 + c * 8];
                *(float4*)(dsm + AT_KV + AT_KVSZ + r * 144 + c * 16) =
                    *(const float4*)&kl[r * 64 + c * 8];
            }
        }
        __syncthreads();

        float acc[2][8][4];
#pragma unroll
        for (int a = 0; a < 2; a++)
#pragma unroll
            for (int b = 0; b < 8; b++)
#pragma unroll
                for (int c = 0; c < 4; c++) acc[a][b][c] = 0.f;

#pragma unroll
        for (int s = 0; s < 4; s++) {
            uint32_t ah[2][4], al[2][4];
#pragma unroll
            for (int mi = 0; mi < 2; mi++) {
                uint32_t ad = sb + AT_Q + (wm + mi * 16 + (lane & 15)) * 144 +
                              s * 32 + ((lane >> 4) & 1) * 16;
                ldsm_x4(ad, ah[mi]);
                ldsm_x4(ad + AT_QSZ, al[mi]);
            }
#pragma unroll
            for (int p = 0; p < 4; p++) {
                uint32_t bh[4], bl[4];
                uint32_t bd = sb + AT_KV +
                    (p * 16 + (lane & 7) + ((lane >> 4) & 1) * 8) * 144 +
                    s * 32 + ((lane >> 3) & 1) * 16;
                ldsm_x4(bd, bh);
                ldsm_x4(bd + AT_KVSZ, bl);
#pragma unroll
                for (int mi = 0; mi < 2; mi++)
#pragma unroll
                    for (int su = 0; su < 2; su++) {
                        mma_bf16(acc[mi][p * 2 + su], ah[mi], &bh[su * 2]);
                        mma_bf16(acc[mi][p * 2 + su], ah[mi], &bl[su * 2]);
                        mma_bf16(acc[mi][p * 2 + su], al[mi], &bh[su * 2]);
                    }
            }
        }
        // write scores to S
#pragma unroll
        for (int mi = 0; mi < 2; mi++)
#pragma unroll
            for (int ni = 0; ni < 8; ni++)
#pragma unroll
                for (int rr = 0; rr < 2; rr++) {
                    int r = wm + mi * 16 + (lane >> 2) + rr * 8;
                    int c = ni * 8 + (lane & 3) * 2;
                    Sf[r * 65 + c]     = acc[mi][ni][rr * 2 + 0];
                    Sf[r * 65 + c + 1] = acc[mi][ni][rr * 2 + 1];
                }
        __syncthreads();
        for (int jj = 0; jj < 64; jj++) e[jc * 64 + jj] = Sf[tid * 65 + jj];
    }

    // ---------------- phase 2: + e2, scale, softmax ----------------
    {
        const int i = tid;
        const float* e2p = &g_e2[(i * NSL + hm) * LQ];
        float mx = -1e30f;
        for (int j = 0; j < LQ; j++) {
            float v = (e[j] + e2p[j]) * 0.125f;
            e[j] = v;
            mx = fmaxf(mx, v);
        }
        float sum = 0.f;
        for (int j = 0; j < LQ; j++) {
            float a = __expf(e[j] - mx);
            e[j] = a;
            sum += a;
        }
        float inv = 1.f / sum;
        for (int j = 0; j < LQ; j++) e[j] *= inv;
    }

    // ---------------- phase 3: z1 = alpha v, alpha -> global bf16 ----------
    float accz[2][8][4];
#pragma unroll
    for (int a = 0; a < 2; a++)
#pragma unroll
        for (int b = 0; b < 8; b++)
#pragma unroll
            for (int c = 0; c < 4; c++) accz[a][b][c] = 0.f;

    for (int jc = 0; jc < 4; jc++) {
        __syncthreads();
        // alpha chunk: convert to bf16 hi/lo -> smem (A operand) + global
        {
            const int i = tid;
            uint32_t ah32[32], al32[32];
#pragma unroll
            for (int w = 0; w < 32; w++) {
                float a0 = e[jc * 64 + w * 2], a1 = e[jc * 64 + w * 2 + 1];
                __nv_bfloat16 h0 = __float2bfloat16(a0);
                __nv_bfloat16 h1 = __float2bfloat16(a1);
                __nv_bfloat162 hp(h0, h1);
                __nv_bfloat162 lp(__float2bfloat16(a0 - __bfloat162float(h0)),
                                  __float2bfloat16(a1 - __bfloat162float(h1)));
                ah32[w] = *(uint32_t*)&hp;
                al32[w] = *(uint32_t*)&lp;
                *(uint32_t*)(dsm + AT_Q + i * 144 + w * 4) = ah32[w];
                *(uint32_t*)(dsm + AT_Q + AT_QSZ + i * 144 + w * 4) = al32[w];
            }
            __nv_bfloat16* gah = &g_ahi[(i * NSL + hm) * LQ + jc * 64];
            __nv_bfloat16* gal = &g_alo[(i * NSL + hm) * LQ + jc * 64];
#pragma unroll
            for (int t = 0; t < 8; t++) {
                *(float4*)&gah[t * 8] = *(float4*)&ah32[t * 4];
                *(float4*)&gal[t * 8] = *(float4*)&al32[t * 4];
            }
        }
        // load V chunk
        {
            const __nv_bfloat16* vh = &g_vhi[(hm * LQ + jc * 64) * DHH];
            const __nv_bfloat16* vl = &g_vlo[(hm * LQ + jc * 64) * DHH];
#pragma unroll
            for (int l = 0; l < 2; l++) {
                int id = tid + l * 256;
                int r = id >> 3, c = id & 7;
                *(float4*)(dsm + AT_KV + r * 144 + c * 16) =
                    *(const float4*)&vh[r * 64 + c * 8];
                *(float4*)(dsm + AT_KV + AT_KVSZ + r * 144 + c * 16) =
                    *(const float4*)&vl[r * 64 + c * 8];
            }
        }
        __syncthreads();

#pragma unroll
        for (int s = 0; s < 4; s++) {
            uint32_t ah[2][4], al[2][4];
#pragma unroll
            for (int mi = 0; mi < 2; mi++) {
                uint32_t ad = sb + AT_Q + (wm + mi * 16 + (lane & 15)) * 144 +
                              s * 32 + ((lane >> 4) & 1) * 16;
                ldsm_x4(ad, ah[mi]);
                ldsm_x4(ad + AT_QSZ, al[mi]);
            }
#pragma unroll
            for (int p = 0; p < 4; p++) {
                uint32_t bh[4], bl[4];
                // V stored [j][d] = [k][n] -> trans ldmatrix
                uint32_t bd = sb + AT_KV + (s * 16 + (lane & 15)) * 144 +
                              p * 32 + ((lane >> 4) & 1) * 16;
                ldsm_x4_t(bd, bh);
                ldsm_x4_t(bd + AT_KVSZ, bl);
#pragma unroll
                for (int mi = 0; mi < 2; mi++)
#pragma unroll
                    for (int su = 0; su < 2; su++) {
                        mma_bf16(accz[mi][p * 2 + su], ah[mi], &bh[su * 2]);
                        mma_bf16(accz[mi][p * 2 + su], ah[mi], &bl[su * 2]);
                        mma_bf16(accz[mi][p * 2 + su], al[mi], &bh[su * 2]);
                    }
            }
        }
    }

    // epilogue: z1 -> global fp32
#pragma unroll
    for (int mi = 0; mi < 2; mi++)
#pragma unroll
        for (int ni = 0; ni < 8; ni++)
#pragma unroll
            for (int rr = 0; rr < 2; rr++) {
                int r = wm + mi * 16 + (lane >> 2) + rr * 8;
                int d = ni * 8 + (lane & 3) * 2;
                *(float2*)&g_z1[(hm * LQ + r) * DHH + d] =
                    make_float2(accz[mi][ni][rr * 2 + 0], accz[mi][ni][rr * 2 + 1]);
            }
}

// ============================================================================
// K4: z2[i][h][d] = sum_{m,j} alpha[i][hm][j] * aV[i][j][d]  (mma + reduce)
// grid (2 halves of hm, 256 i); CTA: 256 rows x 64 d, K=256 in 4 chunks
// ============================================================================
#define Z2_A    0
#define Z2_ASZ  (256 * 144)
#define Z2_KV   (2 * Z2_ASZ)
#define Z2_KVSZ (64 * 144)
#define Z2_TOT  (Z2_KV + 2 * Z2_KVSZ)   // 92160

__global__ __launch_bounds__(256) void z2_mma_kernel()
{
    extern __shared__ __align__(16) unsigned char dsm[];
    const uint32_t sb = smem_to_u32(dsm);
    const int tid = threadIdx.x, lane = tid & 31, wid = tid >> 5;
    const int hm0 = blockIdx.x * 256;
    const int i = blockIdx.y;
    const int wm = wid * 32;

    float acc[2][8][4];
#pragma unroll
    for (int a = 0; a < 2; a++)
#pragma unroll
        for (int b = 0; b < 8; b++)
#pragma unroll
            for (int c = 0; c < 4; c++) acc[a][b][c] = 0.f;

    for (int jc = 0; jc < 4; jc++) {
        __syncthreads();
#pragma unroll
        for (int l = 0; l < 8; l++) {
            int id = tid + l * 256;
            int r = id >> 3, c = id & 7;
            int ga = (i * NSL + hm0 + r) * LQ + jc * 64 + c * 8;
            *(float4*)(dsm + Z2_A + r * 144 + c * 16) = *(const float4*)&g_ahi[ga];
            *(float4*)(dsm + Z2_A + Z2_ASZ + r * 144 + c * 16) = *(const float4*)&g_alo[ga];
        }
#pragma unroll
        for (int l = 0; l < 2; l++) {
            int id = tid + l * 256;
            int r = id >> 3, c = id & 7;
            int gb = (i * LQ + jc * 64 + r) * DHH + c * 8;
            *(float4*)(dsm + Z2_KV + r * 144 + c * 16) = *(const float4*)&g_avhi[gb];
            *(float4*)(dsm + Z2_KV + Z2_KVSZ + r * 144 + c * 16) = *(const float4*)&g_avlo[gb];
        }
        __syncthreads();

#pragma unroll
        for (int s = 0; s < 4; s++) {
            uint32_t ah[2][4], al[2][4];
#pragma unroll
            for (int mi = 0; mi < 2; mi++) {
                uint32_t ad = sb + Z2_A + (wm + mi * 16 + (lane & 15)) * 144 +
                              s * 32 + ((lane >> 4) & 1) * 16;
                ldsm_x4(ad, ah[mi]);
                ldsm_x4(ad + Z2_ASZ, al[mi]);
            }
#pragma unroll
            for (int p = 0; p < 4; p++) {
                uint32_t bh[4], bl[4];
                uint32_t bd = sb + Z2_KV + (s * 16 + (lane & 15)) * 144 +
                              p * 32 + ((lane >> 4) & 1) * 16;
                ldsm_x4_t(bd, bh);
                ldsm_x4_t(bd + Z2_KVSZ, bl);
#pragma unroll
                for (int mi = 0; mi < 2; mi++)
#pragma unroll
                    for (int su = 0; su < 2; su++) {
                        mma_bf16(acc[mi][p * 2 + su], ah[mi], &bh[su * 2]);
                        mma_bf16(acc[mi][p * 2 + su], ah[mi], &bl[su * 2]);
                        mma_bf16(acc[mi][p * 2 + su], al[mi], &bh[su * 2]);
                    }
            }
        }
    }

    // reduce over m (64 rows per h-group) via smem
    __syncthreads();
    float* Sf = (float*)(dsm + Z2_A);   // [256][65]
#pragma unroll
    for (int mi = 0; mi < 2; mi++)
#pragma unroll
        for (int ni = 0; ni < 8; ni++)
#pragma unroll
            for (int rr = 0; rr < 2; rr++) {
                int r = wm + mi * 16 + (lane >> 2) + rr * 8;
                int c = ni * 8 + (lane & 3) * 2;
                Sf[r * 65 + c]     = acc[mi][ni][rr * 2 + 0];
                Sf[r * 65 + c + 1] = acc[mi][ni][rr * 2 + 1];
            }
    __syncthreads();
    {
        int g = tid >> 6, d = tid & 63;
        float s = 0.f;
#pragma unroll 8
        for (int m = 0; m < 64; m++) s += Sf[(g * 64 + m) * 65 + d];
        int h = blockIdx.x * 4 + g;
        g_z2[(i * NH + h) * DHH + d] = s;
    }
}

// =============================================================================
// K5: out[i][h*64+d] = sum_m z1[h*64+m][i][d] + z2[i][h][d]
// =============================================================================
__global__ __launch_bounds__(256) void final_kernel(float* __restrict__ out)
{
    int g    = blockIdx.x * 256 + threadIdx.x;
    int i    = g >> 9;
    int rest = g & 511;
    int h    = rest >> 6;
    int d    = rest & 63;

    const float* zp = &g_z1[((h * NM) * LQ + i) * DHH + d];
    float s = g_z2[(i * NH + h) * DHH + d];
#pragma unroll 8
    for (int m = 0; m < 64; m++) s += zp[m * (LQ * DHH)];
    out[g] = s;
}

// =============================================================================
extern "C" void kernel_launch(void* const* d_in, const int* in_sizes, int n_in,
                              void* d_out, int out_size)
{
    const float* x  = (const float*)d_in[0];
    const float* Wq = (const float*)d_in[1];
    const float* Wk = (const float*)d_in[2];
    const float* Wv = (const float*)d_in[3];
    const float* aK = (const float*)d_in[4];
    const float* aV = (const float*)d_in[5];
    float* out = (float*)d_out;

    cudaFuncSetAttribute(attn_mma_kernel,
                         cudaFuncAttributeMaxDynamicSharedMemorySize, AT_TOT);
    cudaFuncSetAttribute(z2_mma_kernel,
                         cudaFuncAttributeMaxDynamicSharedMemorySize, Z2_TOT);

    __nv_bfloat16 *xhi_p, *xlo_p, *whi_p, *wlo_p, *akhi_p, *aklo_p, *avhi_p, *avlo_p;
    cudaGetSymbolAddress((void**)&xhi_p,  g_xhi);
    cudaGetSymbolAddress((void**)&xlo_p,  g_xlo);
    cudaGetSymbolAddress((void**)&whi_p,  g_whi);
    cudaGetSymbolAddress((void**)&wlo_p,  g_wlo);
    cudaGetSymbolAddress((void**)&akhi_p, g_akhi);
    cudaGetSymbolAddress((void**)&aklo_p, g_aklo);
    cudaGetSymbolAddress((void**)&avhi_p, g_avhi);
    cudaGetSymbolAddress((void**)&avlo_p, g_avlo);

    split_kernel<<<(NTOK * DMOD / 4) / 256, 256>>>(x, xhi_p, xlo_p, NTOK * DMOD / 4);
    split_kernel<<<(DMOD * DMOD / 4) / 256, 256>>>(Wq, whi_p, wlo_p, DMOD * DMOD / 4);
    split_kernel<<<(DMOD * DMOD / 4) / 256, 256>>>(Wk, whi_p + DMOD * DMOD,
                                                   wlo_p + DMOD * DMOD, DMOD * DMOD / 4);
    split_kernel<<<(DMOD * DMOD / 4) / 256, 256>>>(Wv, whi_p + 2 * DMOD * DMOD,
                                                   wlo_p + 2 * DMOD * DMOD, DMOD * DMOD / 4);
    split_kernel<<<(LQ * LQ * DHH / 4) / 256, 256>>>(aK, akhi_p, aklo_p, LQ * LQ * DHH / 4);
    split_kernel<<<(LQ * LQ * DHH / 4) / 256, 256>>>(aV, avhi_p, avlo_p, LQ * LQ * DHH / 4);

    proj_mma_kernel<<<dim3(NTOK / 128, DMOD / 64, 3), 256>>>();
    e2_mma_kernel<<<dim3(4, 4, LQ), 256>>>();
    attn_mma_kernel<<<NSL, 256, AT_TOT>>>();
    z2_mma_kernel<<<dim3(2, LQ), 256, Z2_TOT>>>();
    final_kernel<<<512, 256>>>(out);
}

// round 5
// speedup vs baseline: 2.2265x; 1.2042x over previous
#include <cuda_runtime.h>
#include <cuda_bf16.h>
#include <cstdint>
#include <math.h>

#define LQ   256
#define DHH  64
#define NH   8
#define NM   64
#define NSL  (NH*NM)   // 512
#define DMOD 512
#define NTOK (NM*LQ)   // 16384

// ---------------- scratch -------------
__device__ float g_e2[LQ * NSL * LQ];        // [i][hm][j]
__device__ float g_z1[NSL * LQ * DHH];       // [hm][i][d]
__device__ float g_z2[LQ * NH * DHH];        // [i][h][d]
__device__ float g_invl[NSL * LQ];           // [hm][i]  1/rowsum

__device__ __nv_bfloat16 g_xhi[NTOK * DMOD];
__device__ __nv_bfloat16 g_xlo[NTOK * DMOD];
__device__ __nv_bfloat16 g_whi[3 * DMOD * DMOD];
__device__ __nv_bfloat16 g_wlo[3 * DMOD * DMOD];
__device__ __nv_bfloat16 g_qhi[NSL * LQ * DHH];
__device__ __nv_bfloat16 g_qlo[NSL * LQ * DHH];
__device__ __nv_bfloat16 g_khi[NSL * LQ * DHH];
__device__ __nv_bfloat16 g_klo[NSL * LQ * DHH];
__device__ __nv_bfloat16 g_vhi[NSL * LQ * DHH];
__device__ __nv_bfloat16 g_vlo[NSL * LQ * DHH];
__device__ __nv_bfloat16 g_akhi[LQ * LQ * DHH];
__device__ __nv_bfloat16 g_aklo[LQ * LQ * DHH];
__device__ __nv_bfloat16 g_avhi[LQ * LQ * DHH];
__device__ __nv_bfloat16 g_avlo[LQ * LQ * DHH];
__device__ __nv_bfloat16 g_ahi[LQ * NSL * LQ];   // unnormalized p hi  [i][hm][j]
__device__ __nv_bfloat16 g_alo[LQ * NSL * LQ];

// ========================= helpers ==================================
__device__ __forceinline__ uint32_t smem_to_u32(const void* p) {
    uint32_t a;
    asm("{ .reg .u64 t; cvta.to.shared.u64 t, %1; cvt.u32.u64 %0, t; }"
        : "=r"(a) : "l"(p));
    return a;
}
__device__ __forceinline__ void ldsm_x4(uint32_t addr, uint32_t* r) {
    asm volatile("ldmatrix.sync.aligned.m8n8.x4.shared.b16 {%0,%1,%2,%3}, [%4];"
        : "=r"(r[0]), "=r"(r[1]), "=r"(r[2]), "=r"(r[3]) : "r"(addr));
}
__device__ __forceinline__ void ldsm_x4_t(uint32_t addr, uint32_t* r) {
    asm volatile("ldmatrix.sync.aligned.m8n8.x4.trans.shared.b16 {%0,%1,%2,%3}, [%4];"
        : "=r"(r[0]), "=r"(r[1]), "=r"(r[2]), "=r"(r[3]) : "r"(addr));
}
__device__ __forceinline__ void mma_bf16(float* c, const uint32_t* a,
                                         const uint32_t* b) {
    asm volatile(
        "mma.sync.aligned.m16n8k16.row.col.f32.bf16.bf16.f32 "
        "{%0,%1,%2,%3}, {%4,%5,%6,%7}, {%8,%9}, {%0,%1,%2,%3};"
        : "+f"(c[0]), "+f"(c[1]), "+f"(c[2]), "+f"(c[3])
        : "r"(a[0]), "r"(a[1]), "r"(a[2]), "r"(a[3]), "r"(b[0]), "r"(b[1]));
}
__device__ __forceinline__ uint32_t pack_bf16(float a, float b) {
    __nv_bfloat162 h(__float2bfloat16(a), __float2bfloat16(b));
    return *(uint32_t*)&h;
}

// ============================================================================
// split: fp32 -> (bf16 hi, bf16 lo)
// ============================================================================
__global__ __launch_bounds__(256) void split_kernel(const float* __restrict__ src,
                                                    __nv_bfloat16* __restrict__ hi,
                                                    __nv_bfloat16* __restrict__ lo,
                                                    int nvec)
{
    int idx = blockIdx.x * 256 + threadIdx.x;
    if (idx >= nvec) return;
    float4 v = *(const float4*)&src[idx * 4];
    __nv_bfloat16 h0 = __float2bfloat16(v.x);
    __nv_bfloat16 h1 = __float2bfloat16(v.y);
    __nv_bfloat16 h2 = __float2bfloat16(v.z);
    __nv_bfloat16 h3 = __float2bfloat16(v.w);
    __nv_bfloat162 hp0(h0, h1), hp1(h2, h3);
    __nv_bfloat162 lp0(__float2bfloat16(v.x - __bfloat162float(h0)),
                       __float2bfloat16(v.y - __bfloat162float(h1)));
    __nv_bfloat162 lp1(__float2bfloat16(v.z - __bfloat162float(h2)),
                       __float2bfloat16(v.w - __bfloat162float(h3)));
    *(__nv_bfloat162*)&hi[idx * 4]     = hp0;
    *(__nv_bfloat162*)&hi[idx * 4 + 2] = hp1;
    *(__nv_bfloat162*)&lo[idx * 4]     = lp0;
    *(__nv_bfloat162*)&lo[idx * 4 + 2] = lp1;
}

// ============================================================================
// K1: projection GEMM, CTA 128x128, K=512 in 16 chunks; 8 warps 4m x 2n
// ============================================================================
#define PPITCH 80
#define P_AHI 0
#define P_ALO (128 * PPITCH)
#define P_BHI (2 * 128 * PPITCH)
#define P_BLO (3 * 128 * PPITCH)
#define P_TOT (4 * 128 * PPITCH)   // 40960

__global__ __launch_bounds__(256) void proj_mma_kernel()
{
    __shared__ __align__(16) unsigned char sm[P_TOT];
    const uint32_t sb = smem_to_u32(sm);

    const int tid = threadIdx.x, lane = tid & 31, wid = tid >> 5;
    const int t0 = blockIdx.x * 128;
    const int n0 = blockIdx.y * 128;
    const int sel = blockIdx.z;

    const __nv_bfloat16* Ah = g_xhi;
    const __nv_bfloat16* Al = g_xlo;
    const __nv_bfloat16* Bh = g_whi + sel * DMOD * DMOD;
    const __nv_bfloat16* Bl = g_wlo + sel * DMOD * DMOD;
    __nv_bfloat16 *hip, *lop;
    if (sel == 0)      { hip = g_qhi; lop = g_qlo; }
    else if (sel == 1) { hip = g_khi; lop = g_klo; }
    else               { hip = g_vhi; lop = g_vlo; }

    const int wm = (wid & 3) * 32;
    const int wn = (wid >> 2) * 64;

    float acc[2][8][4];
#pragma unroll
    for (int a = 0; a < 2; a++)
#pragma unroll
        for (int b = 0; b < 8; b++)
#pragma unroll
            for (int c = 0; c < 4; c++) acc[a][b][c] = 0.f;

    for (int ch = 0; ch < 16; ch++) {
        const int k0 = ch * 32;
#pragma unroll
        for (int l = 0; l < 2; l++) {
            int id = tid + l * 256;
            int r = id >> 2, cc = id & 3;
            *(float4*)(sm + P_AHI + r * PPITCH + cc * 16) =
                *(const float4*)&Ah[(t0 + r) * DMOD + k0 + cc * 8];
            *(float4*)(sm + P_ALO + r * PPITCH + cc * 16) =
                *(const float4*)&Al[(t0 + r) * DMOD + k0 + cc * 8];
            *(float4*)(sm + P_BHI + r * PPITCH + cc * 16) =
                *(const float4*)&Bh[(n0 + r) * DMOD + k0 + cc * 8];
            *(float4*)(sm + P_BLO + r * PPITCH + cc * 16) =
                *(const float4*)&Bl[(n0 + r) * DMOD + k0 + cc * 8];
        }
        __syncthreads();

#pragma unroll
        for (int s = 0; s < 2; s++) {
            uint32_t ah[2][4], al[2][4];
#pragma unroll
            for (int mi = 0; mi < 2; mi++) {
                int row = wm + mi * 16 + (lane & 15);
                uint32_t ad = sb + row * PPITCH + s * 32 + ((lane >> 4) & 1) * 16;
                ldsm_x4(ad + P_AHI, ah[mi]);
                ldsm_x4(ad + P_ALO, al[mi]);
            }
#pragma unroll
            for (int p = 0; p < 4; p++) {
                uint32_t bh[4], bl[4];
                int row = wn + p * 16 + (lane & 7) + ((lane >> 4) & 1) * 8;
                uint32_t bd = sb + row * PPITCH + s * 32 + ((lane >> 3) & 1) * 16;
                ldsm_x4(bd + P_BHI, bh);
                ldsm_x4(bd + P_BLO, bl);
#pragma unroll
                for (int mi = 0; mi < 2; mi++)
#pragma unroll
                    for (int su = 0; su < 2; su++) {
                        mma_bf16(acc[mi][p * 2 + su], ah[mi], &bh[su * 2]);
                        mma_bf16(acc[mi][p * 2 + su], ah[mi], &bl[su * 2]);
                        mma_bf16(acc[mi][p * 2 + su], al[mi], &bh[su * 2]);
                    }
            }
        }
        __syncthreads();
    }

#pragma unroll
    for (int mi = 0; mi < 2; mi++)
#pragma unroll
        for (int ni = 0; ni < 8; ni++) {
            int e = n0 + wn + ni * 8 + (lane & 3) * 2;
            int h = e >> 6, d = e & 63;
#pragma unroll
            for (int rr = 0; rr < 2; rr++) {
                int t = t0 + wm + mi * 16 + (lane >> 2) + rr * 8;
                int m = t >> 8, i = t & 255;
                int idx = ((h * NM + m) * LQ + i) * DHH + d;
                float vx = acc[mi][ni][rr * 2 + 0];
                float vy = acc[mi][ni][rr * 2 + 1];
                __nv_bfloat16 h0 = __float2bfloat16(vx);
                __nv_bfloat16 h1 = __float2bfloat16(vy);
                __nv_bfloat162 hp(h0, h1);
                __nv_bfloat162 lp(__float2bfloat16(vx - __bfloat162float(h0)),
                                  __float2bfloat16(vy - __bfloat162float(h1)));
                *(__nv_bfloat162*)&hip[idx] = hp;
                *(__nv_bfloat162*)&lop[idx] = lp;
            }
        }
}

// ============================================================================
// K2: e2[i][hm][j] = sum_d q[hm][i][d] * aK[i][j][d], CTA 128(hm) x 128(j), K=64
// grid (4, 2, 256); 8 warps 4m x 2n; one-shot smem load (pitch 144)
// ============================================================================
#define E2_AHI 0
#define E2_ASZ (128 * 144)       // 18432
#define E2_B   (2 * E2_ASZ)
#define E2_TOT (4 * E2_ASZ)      // 73728

__global__ __launch_bounds__(256) void e2_mma_kernel()
{
    extern __shared__ __align__(16) unsigned char dsm[];
    const uint32_t sb = smem_to_u32(dsm);

    const int tid = threadIdx.x, lane = tid & 31, wid = tid >> 5;
    const int hm0 = blockIdx.x * 128;
    const int j0  = blockIdx.y * 128;
    const int i   = blockIdx.z;
    const int wm = (wid & 3) * 32;
    const int wn = (wid >> 2) * 64;

#pragma unroll
    for (int l = 0; l < 4; l++) {
        int id = tid + l * 256;            // 0..1023
        int r = id >> 3, c = id & 7;
        int ga = ((hm0 + r) * LQ + i) * DHH + c * 8;
        *(float4*)(dsm + E2_AHI + r * 144 + c * 16) = *(const float4*)&g_qhi[ga];
        *(float4*)(dsm + E2_AHI + E2_ASZ + r * 144 + c * 16) = *(const float4*)&g_qlo[ga];
        int gb = (i * LQ + j0 + r) * DHH + c * 8;
        *(float4*)(dsm + E2_B + r * 144 + c * 16) = *(const float4*)&g_akhi[gb];
        *(float4*)(dsm + E2_B + E2_ASZ + r * 144 + c * 16) = *(const float4*)&g_aklo[gb];
    }
    __syncthreads();

    float acc[2][8][4];
#pragma unroll
    for (int a = 0; a < 2; a++)
#pragma unroll
        for (int b = 0; b < 8; b++)
#pragma unroll
            for (int c = 0; c < 4; c++) acc[a][b][c] = 0.f;

#pragma unroll
    for (int s = 0; s < 4; s++) {
        uint32_t ah[2][4], al[2][4];
#pragma unroll
        for (int mi = 0; mi < 2; mi++) {
            uint32_t ad = sb + E2_AHI + (wm + mi * 16 + (lane & 15)) * 144 +
                          s * 32 + ((lane >> 4) & 1) * 16;
            ldsm_x4(ad, ah[mi]);
            ldsm_x4(ad + E2_ASZ, al[mi]);
        }
#pragma unroll
        for (int p = 0; p < 4; p++) {
            uint32_t bh[4], bl[4];
            uint32_t bd = sb + E2_B + (wn + p * 16 + (lane & 7) + ((lane >> 4) & 1) * 8) * 144 +
                          s * 32 + ((lane >> 3) & 1) * 16;
            ldsm_x4(bd, bh);
            ldsm_x4(bd + E2_ASZ, bl);
#pragma unroll
            for (int mi = 0; mi < 2; mi++)
#pragma unroll
                for (int su = 0; su < 2; su++) {
                    mma_bf16(acc[mi][p * 2 + su], ah[mi], &bh[su * 2]);
                    mma_bf16(acc[mi][p * 2 + su], ah[mi], &bl[su * 2]);
                    mma_bf16(acc[mi][p * 2 + su], al[mi], &bh[su * 2]);
                }
        }
    }

#pragma unroll
    for (int mi = 0; mi < 2; mi++)
#pragma unroll
        for (int ni = 0; ni < 8; ni++) {
            int j = j0 + wn + ni * 8 + (lane & 3) * 2;
#pragma unroll
            for (int rr = 0; rr < 2; rr++) {
                int hm = hm0 + wm + mi * 16 + (lane >> 2) + rr * 8;
                *(float2*)&g_e2[(i * NSL + hm) * LQ + j] =
                    make_float2(acc[mi][ni][rr * 2 + 0], acc[mi][ni][rr * 2 + 1]);
            }
        }
}

// ============================================================================
// K3: fused attention, fragment-domain softmax (no max-subtraction),
// C->A register reuse for z1. Writes unnormalized p (hi/lo) + invl.
// ============================================================================
#define A2_KSZ (64 * 144)          // 9216
#define A2_VHI (2 * A2_KSZ)
#define A2_Q   (4 * A2_KSZ)        // 36864
#define A2_QSZ (256 * 144)         // 36864
#define A2_TOT (A2_Q + 2 * A2_QSZ) // 110592

__global__ __launch_bounds__(256) void attn_mma_kernel()
{
    extern __shared__ __align__(16) unsigned char dsm[];
    const uint32_t sb = smem_to_u32(dsm);
    const int tid = threadIdx.x, lane = tid & 31, wid = tid >> 5;
    const int hm = blockIdx.x;
    const int wm = wid * 32;
    const int gr = lane >> 2, qd = lane & 3;

    // resident Q hi/lo
#pragma unroll
    for (int l = 0; l < 8; l++) {
        int id = tid + l * 256;
        int r = id >> 3, c = id & 7;
        int gq = (hm * LQ + r) * DHH + c * 8;
        *(float4*)(dsm + A2_Q + r * 144 + c * 16) = *(const float4*)&g_qhi[gq];
        *(float4*)(dsm + A2_Q + A2_QSZ + r * 144 + c * 16) = *(const float4*)&g_qlo[gq];
    }

    float accz[2][8][4];
#pragma unroll
    for (int a = 0; a < 2; a++)
#pragma unroll
        for (int b = 0; b < 8; b++)
#pragma unroll
            for (int c = 0; c < 4; c++) accz[a][b][c] = 0.f;
    float rsum[2][2] = {{0.f, 0.f}, {0.f, 0.f}};

    for (int jc = 0; jc < 4; jc++) {
        __syncthreads();   // previous chunk's V reads done; Q visible on jc==0
#pragma unroll
        for (int l = 0; l < 2; l++) {
            int id = tid + l * 256;            // 0..511
            int r = id >> 3, c = id & 7;
            int gk = (hm * LQ + jc * 64 + r) * DHH + c * 8;
            *(float4*)(dsm + 0 * A2_KSZ + r * 144 + c * 16) = *(const float4*)&g_khi[gk];
            *(float4*)(dsm + 1 * A2_KSZ + r * 144 + c * 16) = *(const float4*)&g_klo[gk];
            *(float4*)(dsm + 2 * A2_KSZ + r * 144 + c * 16) = *(const float4*)&g_vhi[gk];
            *(float4*)(dsm + 3 * A2_KSZ + r * 144 + c * 16) = *(const float4*)&g_vlo[gk];
        }
        __syncthreads();

        // ---- scores: e1 = q k^T ----
        float acc[2][8][4];
#pragma unroll
        for (int a = 0; a < 2; a++)
#pragma unroll
            for (int b = 0; b < 8; b++)
#pragma unroll
                for (int c = 0; c < 4; c++) acc[a][b][c] = 0.f;

#pragma unroll
        for (int s = 0; s < 4; s++) {
            uint32_t ah[2][4], al[2][4];
#pragma unroll
            for (int mi = 0; mi < 2; mi++) {
                uint32_t ad = sb + A2_Q + (wm + mi * 16 + (lane & 15)) * 144 +
                              s * 32 + ((lane >> 4) & 1) * 16;
                ldsm_x4(ad, ah[mi]);
                ldsm_x4(ad + A2_QSZ, al[mi]);
            }
#pragma unroll
            for (int p = 0; p < 4; p++) {
                uint32_t bh[4], bl[4];
                uint32_t bd = sb + (p * 16 + (lane & 7) + ((lane >> 4) & 1) * 8) * 144 +
                              s * 32 + ((lane >> 3) & 1) * 16;
                ldsm_x4(bd, bh);
                ldsm_x4(bd + A2_KSZ, bl);
#pragma unroll
                for (int mi = 0; mi < 2; mi++)
#pragma unroll
                    for (int su = 0; su < 2; su++) {
                        mma_bf16(acc[mi][p * 2 + su], ah[mi], &bh[su * 2]);
                        mma_bf16(acc[mi][p * 2 + su], ah[mi], &bl[su * 2]);
                        mma_bf16(acc[mi][p * 2 + su], al[mi], &bh[su * 2]);
                    }
            }
        }

        // ---- + e2, scale, exp (no max-shift), rowsum, pack p hi/lo ----
        uint32_t phh[2][8][2], pll[2][8][2];
#pragma unroll
        for (int mi = 0; mi < 2; mi++) {
            int ir0 = wm + mi * 16 + gr;
#pragma unroll
            for (int ni = 0; ni < 8; ni++) {
                int col = jc * 64 + ni * 8 + qd * 2;
                float2 b0 = *(const float2*)&g_e2[(ir0 * NSL + hm) * LQ + col];
                float2 b1 = *(const float2*)&g_e2[((ir0 + 8) * NSL + hm) * LQ + col];
                float e0 = __expf((acc[mi][ni][0] + b0.x) * 0.125f);
                float e1 = __expf((acc[mi][ni][1] + b0.y) * 0.125f);
                float e2v = __expf((acc[mi][ni][2] + b1.x) * 0.125f);
                float e3 = __expf((acc[mi][ni][3] + b1.y) * 0.125f);
                rsum[mi][0] += e0 + e1;
                rsum[mi][1] += e2v + e3;
                uint32_t h01 = pack_bf16(e0, e1);
                uint32_t h23 = pack_bf16(e2v, e3);
                __nv_bfloat162 hh01 = *(__nv_bfloat162*)&h01;
                __nv_bfloat162 hh23 = *(__nv_bfloat162*)&h23;
                uint32_t l01 = pack_bf16(e0 - __bfloat162float(hh01.x),
                                         e1 - __bfloat162float(hh01.y));
                uint32_t l23 = pack_bf16(e2v - __bfloat162float(hh23.x),
                                         e3 - __bfloat162float(hh23.y));
                phh[mi][ni][0] = h01; phh[mi][ni][1] = h23;
                pll[mi][ni][0] = l01; pll[mi][ni][1] = l23;
                *(uint32_t*)&g_ahi[(ir0 * NSL + hm) * LQ + col] = h01;
                *(uint32_t*)&g_ahi[((ir0 + 8) * NSL + hm) * LQ + col] = h23;
                *(uint32_t*)&g_alo[(ir0 * NSL + hm) * LQ + col] = l01;
                *(uint32_t*)&g_alo[((ir0 + 8) * NSL + hm) * LQ + col] = l23;
            }
        }

        // ---- z1 += p V  (A from registers, B via trans ldsm) ----
#pragma unroll
        for (int s = 0; s < 4; s++) {
#pragma unroll
            for (int p = 0; p < 4; p++) {
                uint32_t bh[4], bl[4];
                uint32_t bd = sb + A2_VHI + (s * 16 + (lane & 15)) * 144 +
                              p * 32 + ((lane >> 4) & 1) * 16;
                ldsm_x4_t(bd, bh);
                ldsm_x4_t(bd + A2_KSZ, bl);
#pragma unroll
                for (int mi = 0; mi < 2; mi++) {
                    uint32_t Ahf[4] = {phh[mi][2 * s][0], phh[mi][2 * s][1],
                                       phh[mi][2 * s + 1][0], phh[mi][2 * s + 1][1]};
                    uint32_t Alf[4] = {pll[mi][2 * s][0], pll[mi][2 * s][1],
                                       pll[mi][2 * s + 1][0], pll[mi][2 * s + 1][1]};
#pragma unroll
                    for (int su = 0; su < 2; su++) {
                        mma_bf16(accz[mi][p * 2 + su], Ahf, &bh[su * 2]);
                        mma_bf16(accz[mi][p * 2 + su], Ahf, &bl[su * 2]);
                        mma_bf16(accz[mi][p * 2 + su], Alf, &bh[su * 2]);
                    }
                }
            }
        }
    }

    // ---- finalize: rowsum reduce over quad, write invl, scale + store z1 ----
    float inv[2][2];
#pragma unroll
    for (int mi = 0; mi < 2; mi++)
#pragma unroll
        for (int rr = 0; rr < 2; rr++) {
            float r = rsum[mi][rr];
            r += __shfl_xor_sync(0xffffffffu, r, 1);
            r += __shfl_xor_sync(0xffffffffu, r, 2);
            inv[mi][rr] = 1.f / r;
        }
    if (qd == 0) {
#pragma unroll
        for (int mi = 0; mi < 2; mi++)
#pragma unroll
            for (int rr = 0; rr < 2; rr++)
                g_invl[hm * LQ + wm + mi * 16 + gr + rr * 8] = inv[mi][rr];
    }
#pragma unroll
    for (int mi = 0; mi < 2; mi++)
#pragma unroll
        for (int ni = 0; ni < 8; ni++)
#pragma unroll
            for (int rr = 0; rr < 2; rr++) {
                int r = wm + mi * 16 + gr + rr * 8;
                int d = ni * 8 + qd * 2;
                *(float2*)&g_z1[(hm * LQ + r) * DHH + d] =
                    make_float2(accz[mi][ni][rr * 2 + 0] * inv[mi][rr],
                                accz[mi][ni][rr * 2 + 1] * inv[mi][rr]);
            }
}

// ============================================================================
// K4: z2[i][h][d] = sum_{m,j} (p*invl)[i][hm][j] * aV[i][j][d]
// normalization + hi/lo re-split done during smem staging
// ============================================================================
#define Z2_A    0
#define Z2_ASZ  (256 * 144)
#define Z2_KV   (2 * Z2_ASZ)
#define Z2_KVSZ (64 * 144)
#define Z2_LINV (Z2_KV + 2 * Z2_KVSZ)       // 92160
#define Z2_TOT  (Z2_LINV + 1024)            // 93184

__global__ __launch_bounds__(256) void z2_mma_kernel()
{
    extern __shared__ __align__(16) unsigned char dsm[];
    const uint32_t sb = smem_to_u32(dsm);
    const int tid = threadIdx.x, lane = tid & 31, wid = tid >> 5;
    const int hm0 = blockIdx.x * 256;
    const int i = blockIdx.y;
    const int wm = wid * 32;
    float* linv = (float*)(dsm + Z2_LINV);

    linv[tid] = g_invl[(hm0 + tid) * LQ + i];

    float acc[2][8][4];
#pragma unroll
    for (int a = 0; a < 2; a++)
#pragma unroll
        for (int b = 0; b < 8; b++)
#pragma unroll
            for (int c = 0; c < 4; c++) acc[a][b][c] = 0.f;

    for (int jc = 0; jc < 4; jc++) {
        __syncthreads();
#pragma unroll
        for (int l = 0; l < 8; l++) {
            int id = tid + l * 256;
            int r = id >> 3, c = id & 7;
            int ga = (i * NSL + hm0 + r) * LQ + jc * 64 + c * 8;
            float4 hv = *(const float4*)&g_ahi[ga];
            float4 lv = *(const float4*)&g_alo[ga];
            uint32_t* hw = (uint32_t*)&hv;
            uint32_t* lw = (uint32_t*)&lv;
            float s = linv[r];
#pragma unroll
            for (int w = 0; w < 4; w++) {
                __nv_bfloat162 hh = *(__nv_bfloat162*)&hw[w];
                __nv_bfloat162 ll = *(__nv_bfloat162*)&lw[w];
                float a0 = (__bfloat162float(hh.x) + __bfloat162float(ll.x)) * s;
                float a1 = (__bfloat162float(hh.y) + __bfloat162float(ll.y)) * s;
                uint32_t nh = pack_bf16(a0, a1);
                __nv_bfloat162 nh2 = *(__nv_bfloat162*)&nh;
                uint32_t nl = pack_bf16(a0 - __bfloat162float(nh2.x),
                                        a1 - __bfloat162float(nh2.y));
                hw[w] = nh; lw[w] = nl;
            }
            *(float4*)(dsm + Z2_A + r * 144 + c * 16) = hv;
            *(float4*)(dsm + Z2_A + Z2_ASZ + r * 144 + c * 16) = lv;
        }
#pragma unroll
        for (int l = 0; l < 2; l++) {
            int id = tid + l * 256;
            int r = id >> 3, c = id & 7;
            int gb = (i * LQ + jc * 64 + r) * DHH + c * 8;
            *(float4*)(dsm + Z2_KV + r * 144 + c * 16) = *(const float4*)&g_avhi[gb];
            *(float4*)(dsm + Z2_KV + Z2_KVSZ + r * 144 + c * 16) = *(const float4*)&g_avlo[gb];
        }
        __syncthreads();

#pragma unroll
        for (int s = 0; s < 4; s++) {
            uint32_t ah[2][4], al[2][4];
#pragma unroll
            for (int mi = 0; mi < 2; mi++) {
                uint32_t ad = sb + Z2_A + (wm + mi * 16 + (lane & 15)) * 144 +
                              s * 32 + ((lane >> 4) & 1) * 16;
                ldsm_x4(ad, ah[mi]);
                ldsm_x4(ad + Z2_ASZ, al[mi]);
            }
#pragma unroll
            for (int p = 0; p < 4; p++) {
                uint32_t bh[4], bl[4];
                uint32_t bd = sb + Z2_KV + (s * 16 + (lane & 15)) * 144 +
                              p * 32 + ((lane >> 4) & 1) * 16;
                ldsm_x4_t(bd, bh);
                ldsm_x4_t(bd + Z2_KVSZ, bl);
#pragma unroll
                for (int mi = 0; mi < 2; mi++)
#pragma unroll
                    for (int su = 0; su < 2; su++) {
                        mma_bf16(acc[mi][p * 2 + su], ah[mi], &bh[su * 2]);
                        mma_bf16(acc[mi][p * 2 + su], ah[mi], &bl[su * 2]);
                        mma_bf16(acc[mi][p * 2 + su], al[mi], &bh[su * 2]);
                    }
            }
        }
    }

    // reduce over m via smem
    __syncthreads();
    float* Sf = (float*)(dsm + Z2_A);   // [256][65]
#pragma unroll
    for (int mi = 0; mi < 2; mi++)
#pragma unroll
        for (int ni = 0; ni < 8; ni++)
#pragma unroll
            for (int rr = 0; rr < 2; rr++) {
                int r = wm + mi * 16 + (lane >> 2) + rr * 8;
                int c = ni * 8 + (lane & 3) * 2;
                Sf[r * 65 + c]     = acc[mi][ni][rr * 2 + 0];
                Sf[r * 65 + c + 1] = acc[mi][ni][rr * 2 + 1];
            }
    __syncthreads();
    {
        int g = tid >> 6, d = tid & 63;
        float s = 0.f;
#pragma unroll 8
        for (int m = 0; m < 64; m++) s += Sf[(g * 64 + m) * 65 + d];
        int h = blockIdx.x * 4 + g;
        g_z2[(i * NH + h) * DHH + d] = s;
    }
}

// =============================================================================
// K5: out
// =============================================================================
__global__ __launch_bounds__(256) void final_kernel(float* __restrict__ out)
{
    int g = blockIdx.x * 256 + threadIdx.x;
    int i = g >> 9;
    int rest = g & 511;
    int h = rest >> 6;
    int d = rest & 63;

    const float* zp = &g_z1[((h * NM) * LQ + i) * DHH + d];
    float s = g_z2[(i * NH + h) * DHH + d];
#pragma unroll 8
    for (int m = 0; m < 64; m++) s += zp[m * (LQ * DHH)];
    out[g] = s;
}

// =============================================================================
extern "C" void kernel_launch(void* const* d_in, const int* in_sizes, int n_in,
                              void* d_out, int out_size)
{
    const float* x  = (const float*)d_in[0];
    const float* Wq = (const float*)d_in[1];
    const float* Wk = (const float*)d_in[2];
    const float* Wv = (const float*)d_in[3];
    const float* aK = (const float*)d_in[4];
    const float* aV = (const float*)d_in[5];
    float* out = (float*)d_out;

    cudaFuncSetAttribute(e2_mma_kernel,
                         cudaFuncAttributeMaxDynamicSharedMemorySize, E2_TOT);
    cudaFuncSetAttribute(attn_mma_kernel,
                         cudaFuncAttributeMaxDynamicSharedMemorySize, A2_TOT);
    cudaFuncSetAttribute(z2_mma_kernel,
                         cudaFuncAttributeMaxDynamicSharedMemorySize, Z2_TOT);

    __nv_bfloat16 *xhi_p, *xlo_p, *whi_p, *wlo_p, *akhi_p, *aklo_p, *avhi_p, *avlo_p;
    cudaGetSymbolAddress((void**)&xhi_p,  g_xhi);
    cudaGetSymbolAddress((void**)&xlo_p,  g_xlo);
    cudaGetSymbolAddress((void**)&whi_p,  g_whi);
    cudaGetSymbolAddress((void**)&wlo_p,  g_wlo);
    cudaGetSymbolAddress((void**)&akhi_p, g_akhi);
    cudaGetSymbolAddress((void**)&aklo_p, g_aklo);
    cudaGetSymbolAddress((void**)&avhi_p, g_avhi);
    cudaGetSymbolAddress((void**)&avlo_p, g_avlo);

    split_kernel<<<(NTOK * DMOD / 4) / 256, 256>>>(x, xhi_p, xlo_p, NTOK * DMOD / 4);
    split_kernel<<<(DMOD * DMOD / 4) / 256, 256>>>(Wq, whi_p, wlo_p, DMOD * DMOD / 4);
    split_kernel<<<(DMOD * DMOD / 4) / 256, 256>>>(Wk, whi_p + DMOD * DMOD,
                                                   wlo_p + DMOD * DMOD, DMOD * DMOD / 4);
    split_kernel<<<(DMOD * DMOD / 4) / 256, 256>>>(Wv, whi_p + 2 * DMOD * DMOD,
                                                   wlo_p + 2 * DMOD * DMOD, DMOD * DMOD / 4);
    split_kernel<<<(LQ * LQ * DHH / 4) / 256, 256>>>(aK, akhi_p, aklo_p, LQ * LQ * DHH / 4);
    split_kernel<<<(LQ * LQ * DHH / 4) / 256, 256>>>(aV, avhi_p, avlo_p, LQ * LQ * DHH / 4);

    proj_mma_kernel<<<dim3(NTOK / 128, DMOD / 128, 3), 256>>>();
    e2_mma_kernel<<<dim3(4, 2, LQ), 256, E2_TOT>>>();
    attn_mma_kernel<<<NSL, 256, A2_TOT>>>();
    z2_mma_kernel<<<dim3(2, LQ), 256, Z2_TOT>>>();
    final_kernel<<<512, 256>>>(out);
}

// round 6
// speedup vs baseline: 2.6195x; 1.1765x over previous
#include <cuda_runtime.h>
#include <cuda_bf16.h>
#include <cstdint>
#include <math.h>

#define LQ   256
#define DHH  64
#define NH   8
#define NM   64
#define NSL  (NH*NM)   // 512
#define DMOD 512
#define NTOK (NM*LQ)   // 16384

// ---------------- scratch -------------
__device__ float g_e2[LQ * NSL * LQ];        // [i][hm][j]
__device__ float g_z1[NSL * LQ * DHH];       // [hm][i][d]
__device__ float g_z2[LQ * NH * DHH];        // [i][h][d]
__device__ float g_invl[NSL * LQ];           // [hm][i]  1/rowsum

__device__ __nv_bfloat16 g_xhi[NTOK * DMOD];
__device__ __nv_bfloat16 g_xlo[NTOK * DMOD];
__device__ __nv_bfloat16 g_whi[3 * DMOD * DMOD];
__device__ __nv_bfloat16 g_wlo[3 * DMOD * DMOD];
__device__ __nv_bfloat16 g_qhi[NSL * LQ * DHH];
__device__ __nv_bfloat16 g_qlo[NSL * LQ * DHH];
__device__ __nv_bfloat16 g_khi[NSL * LQ * DHH];
__device__ __nv_bfloat16 g_klo[NSL * LQ * DHH];
__device__ __nv_bfloat16 g_vhi[NSL * LQ * DHH];
__device__ __nv_bfloat16 g_vlo[NSL * LQ * DHH];
__device__ __nv_bfloat16 g_akhi[LQ * LQ * DHH];
__device__ __nv_bfloat16 g_aklo[LQ * LQ * DHH];
__device__ __nv_bfloat16 g_avhi[LQ * LQ * DHH];
__device__ __nv_bfloat16 g_avlo[LQ * LQ * DHH];
__device__ __nv_bfloat16 g_ahi[LQ * NSL * LQ];   // unnormalized p hi  [i][hm][j]
__device__ __nv_bfloat16 g_alo[LQ * NSL * LQ];

// ========================= helpers ==================================
__device__ __forceinline__ uint32_t smem_to_u32(const void* p) {
    uint32_t a;
    asm("{ .reg .u64 t; cvta.to.shared.u64 t, %1; cvt.u32.u64 %0, t; }"
        : "=r"(a) : "l"(p));
    return a;
}
__device__ __forceinline__ void ldsm_x4(uint32_t addr, uint32_t* r) {
    asm volatile("ldmatrix.sync.aligned.m8n8.x4.shared.b16 {%0,%1,%2,%3}, [%4];"
        : "=r"(r[0]), "=r"(r[1]), "=r"(r[2]), "=r"(r[3]) : "r"(addr));
}
__device__ __forceinline__ void ldsm_x4_t(uint32_t addr, uint32_t* r) {
    asm volatile("ldmatrix.sync.aligned.m8n8.x4.trans.shared.b16 {%0,%1,%2,%3}, [%4];"
        : "=r"(r[0]), "=r"(r[1]), "=r"(r[2]), "=r"(r[3]) : "r"(addr));
}
__device__ __forceinline__ void mma_bf16(float* c, const uint32_t* a,
                                         const uint32_t* b) {
    asm volatile(
        "mma.sync.aligned.m16n8k16.row.col.f32.bf16.bf16.f32 "
        "{%0,%1,%2,%3}, {%4,%5,%6,%7}, {%8,%9}, {%0,%1,%2,%3};"
        : "+f"(c[0]), "+f"(c[1]), "+f"(c[2]), "+f"(c[3])
        : "r"(a[0]), "r"(a[1]), "r"(a[2]), "r"(a[3]), "r"(b[0]), "r"(b[1]));
}
__device__ __forceinline__ uint32_t pack_bf16(float a, float b) {
    __nv_bfloat162 h(__float2bfloat16(a), __float2bfloat16(b));
    return *(uint32_t*)&h;
}
__device__ __forceinline__ void cp16(uint32_t s, const void* g) {
    asm volatile("cp.async.cg.shared.global [%0], [%1], 16;"
                 :: "r"(s), "l"(g) : "memory");
}
#define CP_COMMIT() asm volatile("cp.async.commit_group;" ::: "memory")
#define CP_WAIT(n)  asm volatile("cp.async.wait_group %0;" :: "n"(n) : "memory")

// ============================================================================
// split: fp32 -> (bf16 hi, bf16 lo)
// ============================================================================
__global__ __launch_bounds__(256) void split_kernel(const float* __restrict__ src,
                                                    __nv_bfloat16* __restrict__ hi,
                                                    __nv_bfloat16* __restrict__ lo,
                                                    int nvec)
{
    int idx = blockIdx.x * 256 + threadIdx.x;
    if (idx >= nvec) return;
    float4 v = *(const float4*)&src[idx * 4];
    __nv_bfloat16 h0 = __float2bfloat16(v.x);
    __nv_bfloat16 h1 = __float2bfloat16(v.y);
    __nv_bfloat16 h2 = __float2bfloat16(v.z);
    __nv_bfloat16 h3 = __float2bfloat16(v.w);
    __nv_bfloat162 hp0(h0, h1), hp1(h2, h3);
    __nv_bfloat162 lp0(__float2bfloat16(v.x - __bfloat162float(h0)),
                       __float2bfloat16(v.y - __bfloat162float(h1)));
    __nv_bfloat162 lp1(__float2bfloat16(v.z - __bfloat162float(h2)),
                       __float2bfloat16(v.w - __bfloat162float(h3)));
    *(__nv_bfloat162*)&hi[idx * 4]     = hp0;
    *(__nv_bfloat162*)&hi[idx * 4 + 2] = hp1;
    *(__nv_bfloat162*)&lo[idx * 4]     = lp0;
    *(__nv_bfloat162*)&lo[idx * 4 + 2] = lp1;
}

// ============================================================================
// K1: projection GEMM, CTA 128x128, K=512 in 16 chunks; cp.async 2-stage
// smem per stage: Ahi|Alo|Bhi|Blo, each 128 rows x 64B @ pitch 80
// ============================================================================
#define PMAT  (128 * 80)      // 10240
#define PSTG  (4 * PMAT)      // 40960
#define P_TOT (2 * PSTG)      // 81920

__global__ __launch_bounds__(256) void proj_mma_kernel()
{
    extern __shared__ __align__(16) unsigned char dsm[];
    const uint32_t sb = smem_to_u32(dsm);

    const int tid = threadIdx.x, lane = tid & 31, wid = tid >> 5;
    const int t0 = blockIdx.x * 128;
    const int n0 = blockIdx.y * 128;
    const int sel = blockIdx.z;

    const __nv_bfloat16* Ah = g_xhi;
    const __nv_bfloat16* Al = g_xlo;
    const __nv_bfloat16* Bh = g_whi + sel * DMOD * DMOD;
    const __nv_bfloat16* Bl = g_wlo + sel * DMOD * DMOD;
    __nv_bfloat16 *hip, *lop;
    if (sel == 0)      { hip = g_qhi; lop = g_qlo; }
    else if (sel == 1) { hip = g_khi; lop = g_klo; }
    else               { hip = g_vhi; lop = g_vlo; }

    const int wm = (wid & 3) * 32;
    const int wn = (wid >> 2) * 64;

    // per-thread load slots: 8 x cp16; mat = l>>1
    const int lr  = (tid >> 2);          // 0..63
    const int seg = tid & 3;

    auto stage_load = [&](int ch, int st) {
        const int k0 = ch * 32;
        uint32_t s0 = sb + st * PSTG;
#pragma unroll
        for (int l = 0; l < 8; l++) {
            int mat = l >> 1;
            int r = (l & 1) * 64 + lr;
            const __nv_bfloat16* gp;
            int row;
            if (mat == 0)      { gp = Ah; row = t0 + r; }
            else if (mat == 1) { gp = Al; row = t0 + r; }
            else if (mat == 2) { gp = Bh; row = n0 + r; }
            else               { gp = Bl; row = n0 + r; }
            cp16(s0 + mat * PMAT + r * 80 + seg * 16,
                 &gp[row * DMOD + k0 + seg * 8]);
        }
    };

    float acc[2][8][4];
#pragma unroll
    for (int a = 0; a < 2; a++)
#pragma unroll
        for (int b = 0; b < 8; b++)
#pragma unroll
            for (int c = 0; c < 4; c++) acc[a][b][c] = 0.f;

    stage_load(0, 0);
    CP_COMMIT();

    for (int ch = 0; ch < 16; ch++) {
        const int st = ch & 1;
        if (ch + 1 < 16) { stage_load(ch + 1, st ^ 1); CP_COMMIT(); CP_WAIT(1); }
        else             { CP_WAIT(0); }
        __syncthreads();

        const uint32_t s0 = sb + st * PSTG;
#pragma unroll
        for (int s = 0; s < 2; s++) {
            uint32_t ah[2][4], al[2][4];
#pragma unroll
            for (int mi = 0; mi < 2; mi++) {
                int row = wm + mi * 16 + (lane & 15);
                uint32_t ad = s0 + row * 80 + s * 32 + ((lane >> 4) & 1) * 16;
                ldsm_x4(ad, ah[mi]);
                ldsm_x4(ad + PMAT, al[mi]);
            }
#pragma unroll
            for (int p = 0; p < 4; p++) {
                uint32_t bh[4], bl[4];
                int row = wn + p * 16 + (lane & 7) + ((lane >> 4) & 1) * 8;
                uint32_t bd = s0 + 2 * PMAT + row * 80 + s * 32 + ((lane >> 3) & 1) * 16;
                ldsm_x4(bd, bh);
                ldsm_x4(bd + PMAT, bl);
#pragma unroll
                for (int mi = 0; mi < 2; mi++)
#pragma unroll
                    for (int su = 0; su < 2; su++) {
                        mma_bf16(acc[mi][p * 2 + su], ah[mi], &bh[su * 2]);
                        mma_bf16(acc[mi][p * 2 + su], ah[mi], &bl[su * 2]);
                        mma_bf16(acc[mi][p * 2 + su], al[mi], &bh[su * 2]);
                    }
            }
        }
        __syncthreads();
    }

#pragma unroll
    for (int mi = 0; mi < 2; mi++)
#pragma unroll
        for (int ni = 0; ni < 8; ni++) {
            int e = n0 + wn + ni * 8 + (lane & 3) * 2;
            int h = e >> 6, d = e & 63;
#pragma unroll
            for (int rr = 0; rr < 2; rr++) {
                int t = t0 + wm + mi * 16 + (lane >> 2) + rr * 8;
                int m = t >> 8, i = t & 255;
                int idx = ((h * NM + m) * LQ + i) * DHH + d;
                float vx = acc[mi][ni][rr * 2 + 0];
                float vy = acc[mi][ni][rr * 2 + 1];
                __nv_bfloat16 h0 = __float2bfloat16(vx);
                __nv_bfloat16 h1 = __float2bfloat16(vy);
                __nv_bfloat162 hp(h0, h1);
                __nv_bfloat162 lp(__float2bfloat16(vx - __bfloat162float(h0)),
                                  __float2bfloat16(vy - __bfloat162float(h1)));
                *(__nv_bfloat162*)&hip[idx] = hp;
                *(__nv_bfloat162*)&lop[idx] = lp;
            }
        }
}

// ============================================================================
// K2: e2[i][hm][j] = sum_d q[hm][i][d] * aK[i][j][d], CTA 128(hm) x 128(j)
// ============================================================================
#define E2_AHI 0
#define E2_ASZ (128 * 144)
#define E2_B   (2 * E2_ASZ)
#define E2_TOT (4 * E2_ASZ)      // 73728

__global__ __launch_bounds__(256) void e2_mma_kernel()
{
    extern __shared__ __align__(16) unsigned char dsm[];
    const uint32_t sb = smem_to_u32(dsm);

    const int tid = threadIdx.x, lane = tid & 31, wid = tid >> 5;
    const int hm0 = blockIdx.x * 128;
    const int j0  = blockIdx.y * 128;
    const int i   = blockIdx.z;
    const int wm = (wid & 3) * 32;
    const int wn = (wid >> 2) * 64;

#pragma unroll
    for (int l = 0; l < 4; l++) {
        int id = tid + l * 256;
        int r = id >> 3, c = id & 7;
        int ga = ((hm0 + r) * LQ + i) * DHH + c * 8;
        cp16(sb + E2_AHI + r * 144 + c * 16, &g_qhi[ga]);
        cp16(sb + E2_AHI + E2_ASZ + r * 144 + c * 16, &g_qlo[ga]);
        int gb = (i * LQ + j0 + r) * DHH + c * 8;
        cp16(sb + E2_B + r * 144 + c * 16, &g_akhi[gb]);
        cp16(sb + E2_B + E2_ASZ + r * 144 + c * 16, &g_aklo[gb]);
    }
    CP_COMMIT();
    CP_WAIT(0);
    __syncthreads();

    float acc[2][8][4];
#pragma unroll
    for (int a = 0; a < 2; a++)
#pragma unroll
        for (int b = 0; b < 8; b++)
#pragma unroll
            for (int c = 0; c < 4; c++) acc[a][b][c] = 0.f;

#pragma unroll
    for (int s = 0; s < 4; s++) {
        uint32_t ah[2][4], al[2][4];
#pragma unroll
        for (int mi = 0; mi < 2; mi++) {
            uint32_t ad = sb + E2_AHI + (wm + mi * 16 + (lane & 15)) * 144 +
                          s * 32 + ((lane >> 4) & 1) * 16;
            ldsm_x4(ad, ah[mi]);
            ldsm_x4(ad + E2_ASZ, al[mi]);
        }
#pragma unroll
        for (int p = 0; p < 4; p++) {
            uint32_t bh[4], bl[4];
            uint32_t bd = sb + E2_B + (wn + p * 16 + (lane & 7) + ((lane >> 4) & 1) * 8) * 144 +
                          s * 32 + ((lane >> 3) & 1) * 16;
            ldsm_x4(bd, bh);
            ldsm_x4(bd + E2_ASZ, bl);
#pragma unroll
            for (int mi = 0; mi < 2; mi++)
#pragma unroll
                for (int su = 0; su < 2; su++) {
                    mma_bf16(acc[mi][p * 2 + su], ah[mi], &bh[su * 2]);
                    mma_bf16(acc[mi][p * 2 + su], ah[mi], &bl[su * 2]);
                    mma_bf16(acc[mi][p * 2 + su], al[mi], &bh[su * 2]);
                }
        }
    }

#pragma unroll
    for (int mi = 0; mi < 2; mi++)
#pragma unroll
        for (int ni = 0; ni < 8; ni++) {
            int j = j0 + wn + ni * 8 + (lane & 3) * 2;
#pragma unroll
            for (int rr = 0; rr < 2; rr++) {
                int hm = hm0 + wm + mi * 16 + (lane >> 2) + rr * 8;
                *(float2*)&g_e2[(i * NSL + hm) * LQ + j] =
                    make_float2(acc[mi][ni][rr * 2 + 0], acc[mi][ni][rr * 2 + 1]);
            }
        }
}

// ============================================================================
// K3: fused attention (fragment-domain softmax, no max-shift, C->A reuse)
// ============================================================================
#define A2_KSZ (64 * 144)          // 9216
#define A2_VHI (2 * A2_KSZ)
#define A2_Q   (4 * A2_KSZ)        // 36864
#define A2_QSZ (256 * 144)         // 36864
#define A2_TOT (A2_Q + 2 * A2_QSZ) // 110592

__global__ __launch_bounds__(256) void attn_mma_kernel()
{
    extern __shared__ __align__(16) unsigned char dsm[];
    const uint32_t sb = smem_to_u32(dsm);
    const int tid = threadIdx.x, lane = tid & 31, wid = tid >> 5;
    const int hm = blockIdx.x;
    const int wm = wid * 32;
    const int gr = lane >> 2, qd = lane & 3;

    // resident Q hi/lo via cp.async
#pragma unroll
    for (int l = 0; l < 8; l++) {
        int id = tid + l * 256;
        int r = id >> 3, c = id & 7;
        int gq = (hm * LQ + r) * DHH + c * 8;
        cp16(sb + A2_Q + r * 144 + c * 16, &g_qhi[gq]);
        cp16(sb + A2_Q + A2_QSZ + r * 144 + c * 16, &g_qlo[gq]);
    }
    CP_COMMIT();

    float accz[2][8][4];
#pragma unroll
    for (int a = 0; a < 2; a++)
#pragma unroll
        for (int b = 0; b < 8; b++)
#pragma unroll
            for (int c = 0; c < 4; c++) accz[a][b][c] = 0.f;
    float rsum[2][2] = {{0.f, 0.f}, {0.f, 0.f}};

    for (int jc = 0; jc < 4; jc++) {
        __syncthreads();
#pragma unroll
        for (int l = 0; l < 2; l++) {
            int id = tid + l * 256;
            int r = id >> 3, c = id & 7;
            int gk = (hm * LQ + jc * 64 + r) * DHH + c * 8;
            cp16(sb + 0 * A2_KSZ + r * 144 + c * 16, &g_khi[gk]);
            cp16(sb + 1 * A2_KSZ + r * 144 + c * 16, &g_klo[gk]);
            cp16(sb + 2 * A2_KSZ + r * 144 + c * 16, &g_vhi[gk]);
            cp16(sb + 3 * A2_KSZ + r * 144 + c * 16, &g_vlo[gk]);
        }
        CP_COMMIT();
        CP_WAIT(0);
        __syncthreads();

        // ---- scores: e1 = q k^T ----
        float acc[2][8][4];
#pragma unroll
        for (int a = 0; a < 2; a++)
#pragma unroll
            for (int b = 0; b < 8; b++)
#pragma unroll
                for (int c = 0; c < 4; c++) acc[a][b][c] = 0.f;

#pragma unroll
        for (int s = 0; s < 4; s++) {
            uint32_t ah[2][4], al[2][4];
#pragma unroll
            for (int mi = 0; mi < 2; mi++) {
                uint32_t ad = sb + A2_Q + (wm + mi * 16 + (lane & 15)) * 144 +
                              s * 32 + ((lane >> 4) & 1) * 16;
                ldsm_x4(ad, ah[mi]);
                ldsm_x4(ad + A2_QSZ, al[mi]);
            }
#pragma unroll
            for (int p = 0; p < 4; p++) {
                uint32_t bh[4], bl[4];
                uint32_t bd = sb + (p * 16 + (lane & 7) + ((lane >> 4) & 1) * 8) * 144 +
                              s * 32 + ((lane >> 3) & 1) * 16;
                ldsm_x4(bd, bh);
                ldsm_x4(bd + A2_KSZ, bl);
#pragma unroll
                for (int mi = 0; mi < 2; mi++)
#pragma unroll
                    for (int su = 0; su < 2; su++) {
                        mma_bf16(acc[mi][p * 2 + su], ah[mi], &bh[su * 2]);
                        mma_bf16(acc[mi][p * 2 + su], ah[mi], &bl[su * 2]);
                        mma_bf16(acc[mi][p * 2 + su], al[mi], &bh[su * 2]);
                    }
            }
        }

        // ---- + e2, scale, exp, rowsum, pack p hi/lo (e2 loads hoisted) ----
        uint32_t phh[2][8][2], pll[2][8][2];
#pragma unroll
        for (int mi = 0; mi < 2; mi++) {
            int ir0 = wm + mi * 16 + gr;
            float2 e2b0[8], e2b1[8];
#pragma unroll
            for (int ni = 0; ni < 8; ni++) {
                int col = jc * 64 + ni * 8 + qd * 2;
                e2b0[ni] = *(const float2*)&g_e2[(ir0 * NSL + hm) * LQ + col];
                e2b1[ni] = *(const float2*)&g_e2[((ir0 + 8) * NSL + hm) * LQ + col];
            }
#pragma unroll
            for (int ni = 0; ni < 8; ni++) {
                int col = jc * 64 + ni * 8 + qd * 2;
                float e0 = __expf((acc[mi][ni][0] + e2b0[ni].x) * 0.125f);
                float e1 = __expf((acc[mi][ni][1] + e2b0[ni].y) * 0.125f);
                float e2v = __expf((acc[mi][ni][2] + e2b1[ni].x) * 0.125f);
                float e3 = __expf((acc[mi][ni][3] + e2b1[ni].y) * 0.125f);
                rsum[mi][0] += e0 + e1;
                rsum[mi][1] += e2v + e3;
                uint32_t h01 = pack_bf16(e0, e1);
                uint32_t h23 = pack_bf16(e2v, e3);
                __nv_bfloat162 hh01 = *(__nv_bfloat162*)&h01;
                __nv_bfloat162 hh23 = *(__nv_bfloat162*)&h23;
                uint32_t l01 = pack_bf16(e0 - __bfloat162float(hh01.x),
                                         e1 - __bfloat162float(hh01.y));
                uint32_t l23 = pack_bf16(e2v - __bfloat162float(hh23.x),
                                         e3 - __bfloat162float(hh23.y));
                phh[mi][ni][0] = h01; phh[mi][ni][1] = h23;
                pll[mi][ni][0] = l01; pll[mi][ni][1] = l23;
                *(uint32_t*)&g_ahi[(ir0 * NSL + hm) * LQ + col] = h01;
                *(uint32_t*)&g_ahi[((ir0 + 8) * NSL + hm) * LQ + col] = h23;
                *(uint32_t*)&g_alo[(ir0 * NSL + hm) * LQ + col] = l01;
                *(uint32_t*)&g_alo[((ir0 + 8) * NSL + hm) * LQ + col] = l23;
            }
        }

        // ---- z1 += p V ----
#pragma unroll
        for (int s = 0; s < 4; s++) {
#pragma unroll
            for (int p = 0; p < 4; p++) {
                uint32_t bh[4], bl[4];
                uint32_t bd = sb + A2_VHI + (s * 16 + (lane & 15)) * 144 +
                              p * 32 + ((lane >> 4) & 1) * 16;
                ldsm_x4_t(bd, bh);
                ldsm_x4_t(bd + A2_KSZ, bl);
#pragma unroll
                for (int mi = 0; mi < 2; mi++) {
                    uint32_t Ahf[4] = {phh[mi][2 * s][0], phh[mi][2 * s][1],
                                       phh[mi][2 * s + 1][0], phh[mi][2 * s + 1][1]};
                    uint32_t Alf[4] = {pll[mi][2 * s][0], pll[mi][2 * s][1],
                                       pll[mi][2 * s + 1][0], pll[mi][2 * s + 1][1]};
#pragma unroll
                    for (int su = 0; su < 2; su++) {
                        mma_bf16(accz[mi][p * 2 + su], Ahf, &bh[su * 2]);
                        mma_bf16(accz[mi][p * 2 + su], Ahf, &bl[su * 2]);
                        mma_bf16(accz[mi][p * 2 + su], Alf, &bh[su * 2]);
                    }
                }
            }
        }
    }

    // ---- finalize ----
    float inv[2][2];
#pragma unroll
    for (int mi = 0; mi < 2; mi++)
#pragma unroll
        for (int rr = 0; rr < 2; rr++) {
            float r = rsum[mi][rr];
            r += __shfl_xor_sync(0xffffffffu, r, 1);
            r += __shfl_xor_sync(0xffffffffu, r, 2);
            inv[mi][rr] = 1.f / r;
        }
    if (qd == 0) {
#pragma unroll
        for (int mi = 0; mi < 2; mi++)
#pragma unroll
            for (int rr = 0; rr < 2; rr++)
                g_invl[hm * LQ + wm + mi * 16 + gr + rr * 8] = inv[mi][rr];
    }
#pragma unroll
    for (int mi = 0; mi < 2; mi++)
#pragma unroll
        for (int ni = 0; ni < 8; ni++)
#pragma unroll
            for (int rr = 0; rr < 2; rr++) {
                int r = wm + mi * 16 + gr + rr * 8;
                int d = ni * 8 + qd * 2;
                *(float2*)&g_z1[(hm * LQ + r) * DHH + d] =
                    make_float2(accz[mi][ni][rr * 2 + 0] * inv[mi][rr],
                                accz[mi][ni][rr * 2 + 1] * inv[mi][rr]);
            }
}

// ============================================================================
// K4: z2[i][h][d] = sum_{m,j} p[i][hm][j] * aV[i][j][d], scaled by invl in
// the m-reduction (row scaling commutes with the GEMM). Pure cp.async staging.
// ============================================================================
#define Z2_A    0
#define Z2_ASZ  (256 * 144)
#define Z2_KV   (2 * Z2_ASZ)
#define Z2_KVSZ (64 * 144)
#define Z2_LINV (Z2_KV + 2 * Z2_KVSZ)       // 92160
#define Z2_TOT  (Z2_LINV + 1024)            // 93184

__global__ __launch_bounds__(256) void z2_mma_kernel()
{
    extern __shared__ __align__(16) unsigned char dsm[];
    const uint32_t sb = smem_to_u32(dsm);
    const int tid = threadIdx.x, lane = tid & 31, wid = tid >> 5;
    const int hm0 = blockIdx.x * 256;
    const int i = blockIdx.y;
    const int wm = wid * 32;
    float* linv = (float*)(dsm + Z2_LINV);

    linv[tid] = g_invl[(hm0 + tid) * LQ + i];

    float acc[2][8][4];
#pragma unroll
    for (int a = 0; a < 2; a++)
#pragma unroll
        for (int b = 0; b < 8; b++)
#pragma unroll
            for (int c = 0; c < 4; c++) acc[a][b][c] = 0.f;

    for (int jc = 0; jc < 4; jc++) {
        __syncthreads();
#pragma unroll
        for (int l = 0; l < 8; l++) {
            int id = tid + l * 256;
            int r = id >> 3, c = id & 7;
            int ga = (i * NSL + hm0 + r) * LQ + jc * 64 + c * 8;
            cp16(sb + Z2_A + r * 144 + c * 16, &g_ahi[ga]);
            cp16(sb + Z2_A + Z2_ASZ + r * 144 + c * 16, &g_alo[ga]);
        }
#pragma unroll
        for (int l = 0; l < 2; l++) {
            int id = tid + l * 256;
            int r = id >> 3, c = id & 7;
            int gb = (i * LQ + jc * 64 + r) * DHH + c * 8;
            cp16(sb + Z2_KV + r * 144 + c * 16, &g_avhi[gb]);
            cp16(sb + Z2_KV + Z2_KVSZ + r * 144 + c * 16, &g_avlo[gb]);
        }
        CP_COMMIT();
        CP_WAIT(0);
        __syncthreads();

#pragma unroll
        for (int s = 0; s < 4; s++) {
            uint32_t ah[2][4], al[2][4];
#pragma unroll
            for (int mi = 0; mi < 2; mi++) {
                uint32_t ad = sb + Z2_A + (wm + mi * 16 + (lane & 15)) * 144 +
                              s * 32 + ((lane >> 4) & 1) * 16;
                ldsm_x4(ad, ah[mi]);
                ldsm_x4(ad + Z2_ASZ, al[mi]);
            }
#pragma unroll
            for (int p = 0; p < 4; p++) {
                uint32_t bh[4], bl[4];
                uint32_t bd = sb + Z2_KV + (s * 16 + (lane & 15)) * 144 +
                              p * 32 + ((lane >> 4) & 1) * 16;
                ldsm_x4_t(bd, bh);
                ldsm_x4_t(bd + Z2_KVSZ, bl);
#pragma unroll
                for (int mi = 0; mi < 2; mi++)
#pragma unroll
                    for (int su = 0; su < 2; su++) {
                        mma_bf16(acc[mi][p * 2 + su], ah[mi], &bh[su * 2]);
                        mma_bf16(acc[mi][p * 2 + su], ah[mi], &bl[su * 2]);
                        mma_bf16(acc[mi][p * 2 + su], al[mi], &bh[su * 2]);
                    }
            }
        }
    }

    // reduce over m with per-row invl scaling
    __syncthreads();
    float* Sf = (float*)(dsm + Z2_A);   // [256][65]
#pragma unroll
    for (int mi = 0; mi < 2; mi++)
#pragma unroll
        for (int ni = 0; ni < 8; ni++)
#pragma unroll
            for (int rr = 0; rr < 2; rr++) {
                int r = wm + mi * 16 + (lane >> 2) + rr * 8;
                int c = ni * 8 + (lane & 3) * 2;
                Sf[r * 65 + c]     = acc[mi][ni][rr * 2 + 0];
                Sf[r * 65 + c + 1] = acc[mi][ni][rr * 2 + 1];
            }
    __syncthreads();
    {
        int g = tid >> 6, d = tid & 63;
        float s = 0.f;
#pragma unroll 8
        for (int m = 0; m < 64; m++)
            s += Sf[(g * 64 + m) * 65 + d] * linv[g * 64 + m];
        int h = blockIdx.x * 4 + g;
        g_z2[(i * NH + h) * DHH + d] = s;
    }
}

// =============================================================================
// K5: out
// =============================================================================
__global__ __launch_bounds__(256) void final_kernel(float* __restrict__ out)
{
    int g = blockIdx.x * 256 + threadIdx.x;
    int i = g >> 9;
    int rest = g & 511;
    int h = rest >> 6;
    int d = rest & 63;

    const float* zp = &g_z1[((h * NM) * LQ + i) * DHH + d];
    float s = g_z2[(i * NH + h) * DHH + d];
#pragma unroll 8
    for (int m = 0; m < 64; m++) s += zp[m * (LQ * DHH)];
    out[g] = s;
}

// =============================================================================
extern "C" void kernel_launch(void* const* d_in, const int* in_sizes, int n_in,
                              void* d_out, int out_size)
{
    const float* x  = (const float*)d_in[0];
    const float* Wq = (const float*)d_in[1];
    const float* Wk = (const float*)d_in[2];
    const float* Wv = (const float*)d_in[3];
    const float* aK = (const float*)d_in[4];
    const float* aV = (const float*)d_in[5];
    float* out = (float*)d_out;

    cudaFuncSetAttribute(proj_mma_kernel,
                         cudaFuncAttributeMaxDynamicSharedMemorySize, P_TOT);
    cudaFuncSetAttribute(e2_mma_kernel,
                         cudaFuncAttributeMaxDynamicSharedMemorySize, E2_TOT);
    cudaFuncSetAttribute(attn_mma_kernel,
                         cudaFuncAttributeMaxDynamicSharedMemorySize, A2_TOT);
    cudaFuncSetAttribute(z2_mma_kernel,
                         cudaFuncAttributeMaxDynamicSharedMemorySize, Z2_TOT);

    __nv_bfloat16 *xhi_p, *xlo_p, *whi_p, *wlo_p, *akhi_p, *aklo_p, *avhi_p, *avlo_p;
    cudaGetSymbolAddress((void**)&xhi_p,  g_xhi);
    cudaGetSymbolAddress((void**)&xlo_p,  g_xlo);
    cudaGetSymbolAddress((void**)&whi_p,  g_whi);
    cudaGetSymbolAddress((void**)&wlo_p,  g_wlo);
    cudaGetSymbolAddress((void**)&akhi_p, g_akhi);
    cudaGetSymbolAddress((void**)&aklo_p, g_aklo);
    cudaGetSymbolAddress((void**)&avhi_p, g_avhi);
    cudaGetSymbolAddress((void**)&avlo_p, g_avlo);

    split_kernel<<<(NTOK * DMOD / 4) / 256, 256>>>(x, xhi_p, xlo_p, NTOK * DMOD / 4);
    split_kernel<<<(DMOD * DMOD / 4) / 256, 256>>>(Wq, whi_p, wlo_p, DMOD * DMOD / 4);
    split_kernel<<<(DMOD * DMOD / 4) / 256, 256>>>(Wk, whi_p + DMOD * DMOD,
                                                   wlo_p + DMOD * DMOD, DMOD * DMOD / 4);
    split_kernel<<<(DMOD * DMOD / 4) / 256, 256>>>(Wv, whi_p + 2 * DMOD * DMOD,
                                                   wlo_p + 2 * DMOD * DMOD, DMOD * DMOD / 4);
    split_kernel<<<(LQ * LQ * DHH / 4) / 256, 256>>>(aK, akhi_p, aklo_p, LQ * LQ * DHH / 4);
    split_kernel<<<(LQ * LQ * DHH / 4) / 256, 256>>>(aV, avhi_p, avlo_p, LQ * LQ * DHH / 4);

    proj_mma_kernel<<<dim3(NTOK / 128, DMOD / 128, 3), 256, P_TOT>>>();
    e2_mma_kernel<<<dim3(4, 2, LQ), 256, E2_TOT>>>();
    attn_mma_kernel<<<NSL, 256, A2_TOT>>>();
    z2_mma_kernel<<<dim3(2, LQ), 256, Z2_TOT>>>();
    final_kernel<<<512, 256>>>(out);
}

// round 7
// speedup vs baseline: 2.7435x; 1.0473x over previous
#include <cuda_runtime.h>
#include <cuda_bf16.h>
#include <cstdint>
#include <math.h>

#define LQ   256
#define DHH  64
#define NH   8
#define NM   64
#define NSL  (NH*NM)   // 512
#define DMOD 512
#define NTOK (NM*LQ)   // 16384

// ---------------- scratch -------------
__device__ float g_e2[LQ * NSL * LQ];        // [i][hm][j]
__device__ float g_z1[NSL * LQ * DHH];       // [hm][i][d]
__device__ float g_z2[LQ * NH * DHH];        // [i][h][d]
__device__ float g_invl[NSL * LQ];           // [hm][i]  1/rowsum

__device__ __nv_bfloat16 g_xhi[NTOK * DMOD];
__device__ __nv_bfloat16 g_xlo[NTOK * DMOD];
__device__ __nv_bfloat16 g_whi[3 * DMOD * DMOD];
__device__ __nv_bfloat16 g_wlo[3 * DMOD * DMOD];
__device__ __nv_bfloat16 g_qhi[NSL * LQ * DHH];
__device__ __nv_bfloat16 g_qlo[NSL * LQ * DHH];
__device__ __nv_bfloat16 g_khi[NSL * LQ * DHH];
__device__ __nv_bfloat16 g_klo[NSL * LQ * DHH];
__device__ __nv_bfloat16 g_vhi[NSL * LQ * DHH];
__device__ __nv_bfloat16 g_vlo[NSL * LQ * DHH];
__device__ __nv_bfloat16 g_akhi[LQ * LQ * DHH];
__device__ __nv_bfloat16 g_aklo[LQ * LQ * DHH];
__device__ __nv_bfloat16 g_avhi[LQ * LQ * DHH];
__device__ __nv_bfloat16 g_avlo[LQ * LQ * DHH];
__device__ __nv_bfloat16 g_ahi[LQ * NSL * LQ];   // unnormalized p hi  [i][hm][j]
__device__ __nv_bfloat16 g_alo[LQ * NSL * LQ];

// ========================= helpers ==================================
__device__ __forceinline__ uint32_t smem_to_u32(const void* p) {
    uint32_t a;
    asm("{ .reg .u64 t; cvta.to.shared.u64 t, %1; cvt.u32.u64 %0, t; }"
        : "=r"(a) : "l"(p));
    return a;
}
__device__ __forceinline__ void ldsm_x4(uint32_t addr, uint32_t* r) {
    asm volatile("ldmatrix.sync.aligned.m8n8.x4.shared.b16 {%0,%1,%2,%3}, [%4];"
        : "=r"(r[0]), "=r"(r[1]), "=r"(r[2]), "=r"(r[3]) : "r"(addr));
}
__device__ __forceinline__ void ldsm_x4_t(uint32_t addr, uint32_t* r) {
    asm volatile("ldmatrix.sync.aligned.m8n8.x4.trans.shared.b16 {%0,%1,%2,%3}, [%4];"
        : "=r"(r[0]), "=r"(r[1]), "=r"(r[2]), "=r"(r[3]) : "r"(addr));
}
__device__ __forceinline__ void mma_bf16(float* c, const uint32_t* a,
                                         const uint32_t* b) {
    asm volatile(
        "mma.sync.aligned.m16n8k16.row.col.f32.bf16.bf16.f32 "
        "{%0,%1,%2,%3}, {%4,%5,%6,%7}, {%8,%9}, {%0,%1,%2,%3};"
        : "+f"(c[0]), "+f"(c[1]), "+f"(c[2]), "+f"(c[3])
        : "r"(a[0]), "r"(a[1]), "r"(a[2]), "r"(a[3]), "r"(b[0]), "r"(b[1]));
}
__device__ __forceinline__ uint32_t pack_bf16(float a, float b) {
    __nv_bfloat162 h(__float2bfloat16(a), __float2bfloat16(b));
    return *(uint32_t*)&h;
}
__device__ __forceinline__ void cp16(uint32_t s, const void* g) {
    asm volatile("cp.async.cg.shared.global [%0], [%1], 16;"
                 :: "r"(s), "l"(g) : "memory");
}
#define CP_COMMIT() asm volatile("cp.async.commit_group;" ::: "memory")
#define CP_WAIT(n)  asm volatile("cp.async.wait_group %0;" :: "n"(n) : "memory")

// ============================================================================
// merged split: fp32 -> (bf16 hi, bf16 lo) for all 6 tensors in one launch
// ============================================================================
struct SplitArgs {
    const float* src[6];
    __nv_bfloat16* hi[6];
    __nv_bfloat16* lo[6];
    int off[7];    // vec4 prefix offsets
};

__global__ __launch_bounds__(256) void split_all_kernel(SplitArgs a)
{
    int total = a.off[6];
    for (int idx = blockIdx.x * 256 + threadIdx.x; idx < total;
         idx += gridDim.x * 256) {
        int seg = 0;
#pragma unroll
        for (int s = 1; s < 6; s++) if (idx >= a.off[s]) seg = s;
        int li = idx - a.off[seg];
        float4 v = *(const float4*)&a.src[seg][li * 4];
        __nv_bfloat16 h0 = __float2bfloat16(v.x);
        __nv_bfloat16 h1 = __float2bfloat16(v.y);
        __nv_bfloat16 h2 = __float2bfloat16(v.z);
        __nv_bfloat16 h3 = __float2bfloat16(v.w);
        __nv_bfloat162 hp0(h0, h1), hp1(h2, h3);
        __nv_bfloat162 lp0(__float2bfloat16(v.x - __bfloat162float(h0)),
                           __float2bfloat16(v.y - __bfloat162float(h1)));
        __nv_bfloat162 lp1(__float2bfloat16(v.z - __bfloat162float(h2)),
                           __float2bfloat16(v.w - __bfloat162float(h3)));
        *(__nv_bfloat162*)&a.hi[seg][li * 4]     = hp0;
        *(__nv_bfloat162*)&a.hi[seg][li * 4 + 2] = hp1;
        *(__nv_bfloat162*)&a.lo[seg][li * 4]     = lp0;
        *(__nv_bfloat162*)&a.lo[seg][li * 4 + 2] = lp1;
    }
}

// ============================================================================
// K1: projection GEMM, CTA 128x128, K=512 in 16 chunks; cp.async 2-stage
// ============================================================================
#define PMAT  (128 * 80)      // 10240
#define PSTG  (4 * PMAT)      // 40960
#define P_TOT (2 * PSTG)      // 81920

__global__ __launch_bounds__(256) void proj_mma_kernel()
{
    extern __shared__ __align__(16) unsigned char dsm[];
    const uint32_t sb = smem_to_u32(dsm);

    const int tid = threadIdx.x, lane = tid & 31, wid = tid >> 5;
    const int t0 = blockIdx.x * 128;
    const int n0 = blockIdx.y * 128;
    const int sel = blockIdx.z;

    const __nv_bfloat16* Ah = g_xhi;
    const __nv_bfloat16* Al = g_xlo;
    const __nv_bfloat16* Bh = g_whi + sel * DMOD * DMOD;
    const __nv_bfloat16* Bl = g_wlo + sel * DMOD * DMOD;
    __nv_bfloat16 *hip, *lop;
    if (sel == 0)      { hip = g_qhi; lop = g_qlo; }
    else if (sel == 1) { hip = g_khi; lop = g_klo; }
    else               { hip = g_vhi; lop = g_vlo; }

    const int wm = (wid & 3) * 32;
    const int wn = (wid >> 2) * 64;
    const int lr  = (tid >> 2);
    const int seg = tid & 3;

    auto stage_load = [&](int ch, int st) {
        const int k0 = ch * 32;
        uint32_t s0 = sb + st * PSTG;
#pragma unroll
        for (int l = 0; l < 8; l++) {
            int mat = l >> 1;
            int r = (l & 1) * 64 + lr;
            const __nv_bfloat16* gp;
            int row;
            if (mat == 0)      { gp = Ah; row = t0 + r; }
            else if (mat == 1) { gp = Al; row = t0 + r; }
            else if (mat == 2) { gp = Bh; row = n0 + r; }
            else               { gp = Bl; row = n0 + r; }
            cp16(s0 + mat * PMAT + r * 80 + seg * 16,
                 &gp[row * DMOD + k0 + seg * 8]);
        }
    };

    float acc[2][8][4];
#pragma unroll
    for (int a = 0; a < 2; a++)
#pragma unroll
        for (int b = 0; b < 8; b++)
#pragma unroll
            for (int c = 0; c < 4; c++) acc[a][b][c] = 0.f;

    stage_load(0, 0);
    CP_COMMIT();

    for (int ch = 0; ch < 16; ch++) {
        const int st = ch & 1;
        if (ch + 1 < 16) { stage_load(ch + 1, st ^ 1); CP_COMMIT(); CP_WAIT(1); }
        else             { CP_WAIT(0); }
        __syncthreads();

        const uint32_t s0 = sb + st * PSTG;
#pragma unroll
        for (int s = 0; s < 2; s++) {
            uint32_t ah[2][4], al[2][4];
#pragma unroll
            for (int mi = 0; mi < 2; mi++) {
                int row = wm + mi * 16 + (lane & 15);
                uint32_t ad = s0 + row * 80 + s * 32 + ((lane >> 4) & 1) * 16;
                ldsm_x4(ad, ah[mi]);
                ldsm_x4(ad + PMAT, al[mi]);
            }
#pragma unroll
            for (int p = 0; p < 4; p++) {
                uint32_t bh[4], bl[4];
                int row = wn + p * 16 + (lane & 7) + ((lane >> 4) & 1) * 8;
                uint32_t bd = s0 + 2 * PMAT + row * 80 + s * 32 + ((lane >> 3) & 1) * 16;
                ldsm_x4(bd, bh);
                ldsm_x4(bd + PMAT, bl);
#pragma unroll
                for (int mi = 0; mi < 2; mi++)
#pragma unroll
                    for (int su = 0; su < 2; su++) {
                        mma_bf16(acc[mi][p * 2 + su], ah[mi], &bh[su * 2]);
                        mma_bf16(acc[mi][p * 2 + su], ah[mi], &bl[su * 2]);
                        mma_bf16(acc[mi][p * 2 + su], al[mi], &bh[su * 2]);
                    }
            }
        }
        __syncthreads();
    }

#pragma unroll
    for (int mi = 0; mi < 2; mi++)
#pragma unroll
        for (int ni = 0; ni < 8; ni++) {
            int e = n0 + wn + ni * 8 + (lane & 3) * 2;
            int h = e >> 6, d = e & 63;
#pragma unroll
            for (int rr = 0; rr < 2; rr++) {
                int t = t0 + wm + mi * 16 + (lane >> 2) + rr * 8;
                int m = t >> 8, i = t & 255;
                int idx = ((h * NM + m) * LQ + i) * DHH + d;
                float vx = acc[mi][ni][rr * 2 + 0];
                float vy = acc[mi][ni][rr * 2 + 1];
                __nv_bfloat16 h0 = __float2bfloat16(vx);
                __nv_bfloat16 h1 = __float2bfloat16(vy);
                __nv_bfloat162 hp(h0, h1);
                __nv_bfloat162 lp(__float2bfloat16(vx - __bfloat162float(h0)),
                                  __float2bfloat16(vy - __bfloat162float(h1)));
                *(__nv_bfloat162*)&hip[idx] = hp;
                *(__nv_bfloat162*)&lop[idx] = lp;
            }
        }
}

// ============================================================================
// K2: e2[i][hm][j], CTA 128(hm) x 128(j), K=64 one-shot
// ============================================================================
#define E2_AHI 0
#define E2_ASZ (128 * 144)
#define E2_B   (2 * E2_ASZ)
#define E2_TOT (4 * E2_ASZ)      // 73728

__global__ __launch_bounds__(256) void e2_mma_kernel()
{
    extern __shared__ __align__(16) unsigned char dsm[];
    const uint32_t sb = smem_to_u32(dsm);

    const int tid = threadIdx.x, lane = tid & 31, wid = tid >> 5;
    const int hm0 = blockIdx.x * 128;
    const int j0  = blockIdx.y * 128;
    const int i   = blockIdx.z;
    const int wm = (wid & 3) * 32;
    const int wn = (wid >> 2) * 64;

#pragma unroll
    for (int l = 0; l < 4; l++) {
        int id = tid + l * 256;
        int r = id >> 3, c = id & 7;
        int ga = ((hm0 + r) * LQ + i) * DHH + c * 8;
        cp16(sb + E2_AHI + r * 144 + c * 16, &g_qhi[ga]);
        cp16(sb + E2_AHI + E2_ASZ + r * 144 + c * 16, &g_qlo[ga]);
        int gb = (i * LQ + j0 + r) * DHH + c * 8;
        cp16(sb + E2_B + r * 144 + c * 16, &g_akhi[gb]);
        cp16(sb + E2_B + E2_ASZ + r * 144 + c * 16, &g_aklo[gb]);
    }
    CP_COMMIT();
    CP_WAIT(0);
    __syncthreads();

    float acc[2][8][4];
#pragma unroll
    for (int a = 0; a < 2; a++)
#pragma unroll
        for (int b = 0; b < 8; b++)
#pragma unroll
            for (int c = 0; c < 4; c++) acc[a][b][c] = 0.f;

#pragma unroll
    for (int s = 0; s < 4; s++) {
        uint32_t ah[2][4], al[2][4];
#pragma unroll
        for (int mi = 0; mi < 2; mi++) {
            uint32_t ad = sb + E2_AHI + (wm + mi * 16 + (lane & 15)) * 144 +
                          s * 32 + ((lane >> 4) & 1) * 16;
            ldsm_x4(ad, ah[mi]);
            ldsm_x4(ad + E2_ASZ, al[mi]);
        }
#pragma unroll
        for (int p = 0; p < 4; p++) {
            uint32_t bh[4], bl[4];
            uint32_t bd = sb + E2_B + (wn + p * 16 + (lane & 7) + ((lane >> 4) & 1) * 8) * 144 +
                          s * 32 + ((lane >> 3) & 1) * 16;
            ldsm_x4(bd, bh);
            ldsm_x4(bd + E2_ASZ, bl);
#pragma unroll
            for (int mi = 0; mi < 2; mi++)
#pragma unroll
                for (int su = 0; su < 2; su++) {
                    mma_bf16(acc[mi][p * 2 + su], ah[mi], &bh[su * 2]);
                    mma_bf16(acc[mi][p * 2 + su], ah[mi], &bl[su * 2]);
                    mma_bf16(acc[mi][p * 2 + su], al[mi], &bh[su * 2]);
                }
        }
    }

#pragma unroll
    for (int mi = 0; mi < 2; mi++)
#pragma unroll
        for (int ni = 0; ni < 8; ni++) {
            int j = j0 + wn + ni * 8 + (lane & 3) * 2;
#pragma unroll
            for (int rr = 0; rr < 2; rr++) {
                int hm = hm0 + wm + mi * 16 + (lane >> 2) + rr * 8;
                *(float2*)&g_e2[(i * NSL + hm) * LQ + j] =
                    make_float2(acc[mi][ni][rr * 2 + 0], acc[mi][ni][rr * 2 + 1]);
            }
        }
}

// ============================================================================
// K3: fused attention, double-buffered K/V stages
// smem: KV stage x2 (4 mats x 9216) | Q hi/lo
// ============================================================================
#define A2_KSZ  (64 * 144)           // 9216
#define A2_STG  (4 * A2_KSZ)         // 36864
#define A2_Q    (2 * A2_STG)         // 73728
#define A2_QSZ  (256 * 144)          // 36864
#define A2_TOT  (A2_Q + 2 * A2_QSZ)  // 147456

__global__ __launch_bounds__(256) void attn_mma_kernel()
{
    extern __shared__ __align__(16) unsigned char dsm[];
    const uint32_t sb = smem_to_u32(dsm);
    const int tid = threadIdx.x, lane = tid & 31, wid = tid >> 5;
    const int hm = blockIdx.x;
    const int wm = wid * 32;
    const int gr = lane >> 2, qd = lane & 3;

    auto load_kv = [&](int jc, int st) {
        uint32_t s0 = sb + st * A2_STG;
#pragma unroll
        for (int l = 0; l < 2; l++) {
            int id = tid + l * 256;
            int r = id >> 3, c = id & 7;
            int gk = (hm * LQ + jc * 64 + r) * DHH + c * 8;
            cp16(s0 + 0 * A2_KSZ + r * 144 + c * 16, &g_khi[gk]);
            cp16(s0 + 1 * A2_KSZ + r * 144 + c * 16, &g_klo[gk]);
            cp16(s0 + 2 * A2_KSZ + r * 144 + c * 16, &g_vhi[gk]);
            cp16(s0 + 3 * A2_KSZ + r * 144 + c * 16, &g_vlo[gk]);
        }
    };

    // Q resident
#pragma unroll
    for (int l = 0; l < 8; l++) {
        int id = tid + l * 256;
        int r = id >> 3, c = id & 7;
        int gq = (hm * LQ + r) * DHH + c * 8;
        cp16(sb + A2_Q + r * 144 + c * 16, &g_qhi[gq]);
        cp16(sb + A2_Q + A2_QSZ + r * 144 + c * 16, &g_qlo[gq]);
    }
    CP_COMMIT();
    load_kv(0, 0);
    CP_COMMIT();

    float accz[2][8][4];
#pragma unroll
    for (int a = 0; a < 2; a++)
#pragma unroll
        for (int b = 0; b < 8; b++)
#pragma unroll
            for (int c = 0; c < 4; c++) accz[a][b][c] = 0.f;
    float rsum[2][2] = {{0.f, 0.f}, {0.f, 0.f}};

    for (int jc = 0; jc < 4; jc++) {
        const int st = jc & 1;
        __syncthreads();   // all reads of stage st^1 (iter jc-1) done
        if (jc < 3) { load_kv(jc + 1, st ^ 1); CP_COMMIT(); CP_WAIT(1); }
        else        { CP_WAIT(0); }
        __syncthreads();

        const uint32_t s0 = sb + st * A2_STG;

        // ---- scores: e1 = q k^T ----
        float acc[2][8][4];
#pragma unroll
        for (int a = 0; a < 2; a++)
#pragma unroll
            for (int b = 0; b < 8; b++)
#pragma unroll
                for (int c = 0; c < 4; c++) acc[a][b][c] = 0.f;

#pragma unroll
        for (int s = 0; s < 4; s++) {
            uint32_t ah[2][4], al[2][4];
#pragma unroll
            for (int mi = 0; mi < 2; mi++) {
                uint32_t ad = sb + A2_Q + (wm + mi * 16 + (lane & 15)) * 144 +
                              s * 32 + ((lane >> 4) & 1) * 16;
                ldsm_x4(ad, ah[mi]);
                ldsm_x4(ad + A2_QSZ, al[mi]);
            }
#pragma unroll
            for (int p = 0; p < 4; p++) {
                uint32_t bh[4], bl[4];
                uint32_t bd = s0 + (p * 16 + (lane & 7) + ((lane >> 4) & 1) * 8) * 144 +
                              s * 32 + ((lane >> 3) & 1) * 16;
                ldsm_x4(bd, bh);
                ldsm_x4(bd + A2_KSZ, bl);
#pragma unroll
                for (int mi = 0; mi < 2; mi++)
#pragma unroll
                    for (int su = 0; su < 2; su++) {
                        mma_bf16(acc[mi][p * 2 + su], ah[mi], &bh[su * 2]);
                        mma_bf16(acc[mi][p * 2 + su], ah[mi], &bl[su * 2]);
                        mma_bf16(acc[mi][p * 2 + su], al[mi], &bh[su * 2]);
                    }
            }
        }

        // ---- + e2, scale, exp, rowsum, pack p hi/lo ----
        uint32_t phh[2][8][2], pll[2][8][2];
#pragma unroll
        for (int mi = 0; mi < 2; mi++) {
            int ir0 = wm + mi * 16 + gr;
            float2 e2b0[8], e2b1[8];
#pragma unroll
            for (int ni = 0; ni < 8; ni++) {
                int col = jc * 64 + ni * 8 + qd * 2;
                e2b0[ni] = *(const float2*)&g_e2[(ir0 * NSL + hm) * LQ + col];
                e2b1[ni] = *(const float2*)&g_e2[((ir0 + 8) * NSL + hm) * LQ + col];
            }
#pragma unroll
            for (int ni = 0; ni < 8; ni++) {
                int col = jc * 64 + ni * 8 + qd * 2;
                float e0 = __expf((acc[mi][ni][0] + e2b0[ni].x) * 0.125f);
                float e1 = __expf((acc[mi][ni][1] + e2b0[ni].y) * 0.125f);
                float e2v = __expf((acc[mi][ni][2] + e2b1[ni].x) * 0.125f);
                float e3 = __expf((acc[mi][ni][3] + e2b1[ni].y) * 0.125f);
                rsum[mi][0] += e0 + e1;
                rsum[mi][1] += e2v + e3;
                uint32_t h01 = pack_bf16(e0, e1);
                uint32_t h23 = pack_bf16(e2v, e3);
                __nv_bfloat162 hh01 = *(__nv_bfloat162*)&h01;
                __nv_bfloat162 hh23 = *(__nv_bfloat162*)&h23;
                uint32_t l01 = pack_bf16(e0 - __bfloat162float(hh01.x),
                                         e1 - __bfloat162float(hh01.y));
                uint32_t l23 = pack_bf16(e2v - __bfloat162float(hh23.x),
                                         e3 - __bfloat162float(hh23.y));
                phh[mi][ni][0] = h01; phh[mi][ni][1] = h23;
                pll[mi][ni][0] = l01; pll[mi][ni][1] = l23;
                *(uint32_t*)&g_ahi[(ir0 * NSL + hm) * LQ + col] = h01;
                *(uint32_t*)&g_ahi[((ir0 + 8) * NSL + hm) * LQ + col] = h23;
                *(uint32_t*)&g_alo[(ir0 * NSL + hm) * LQ + col] = l01;
                *(uint32_t*)&g_alo[((ir0 + 8) * NSL + hm) * LQ + col] = l23;
            }
        }

        // ---- z1 += p V ----
#pragma unroll
        for (int s = 0; s < 4; s++) {
#pragma unroll
            for (int p = 0; p < 4; p++) {
                uint32_t bh[4], bl[4];
                uint32_t bd = s0 + 2 * A2_KSZ + (s * 16 + (lane & 15)) * 144 +
                              p * 32 + ((lane >> 4) & 1) * 16;
                ldsm_x4_t(bd, bh);
                ldsm_x4_t(bd + A2_KSZ, bl);
#pragma unroll
                for (int mi = 0; mi < 2; mi++) {
                    uint32_t Ahf[4] = {phh[mi][2 * s][0], phh[mi][2 * s][1],
                                       phh[mi][2 * s + 1][0], phh[mi][2 * s + 1][1]};
                    uint32_t Alf[4] = {pll[mi][2 * s][0], pll[mi][2 * s][1],
                                       pll[mi][2 * s + 1][0], pll[mi][2 * s + 1][1]};
#pragma unroll
                    for (int su = 0; su < 2; su++) {
                        mma_bf16(accz[mi][p * 2 + su], Ahf, &bh[su * 2]);
                        mma_bf16(accz[mi][p * 2 + su], Ahf, &bl[su * 2]);
                        mma_bf16(accz[mi][p * 2 + su], Alf, &bh[su * 2]);
                    }
                }
            }
        }
    }

    // ---- finalize ----
    float inv[2][2];
#pragma unroll
    for (int mi = 0; mi < 2; mi++)
#pragma unroll
        for (int rr = 0; rr < 2; rr++) {
            float r = rsum[mi][rr];
            r += __shfl_xor_sync(0xffffffffu, r, 1);
            r += __shfl_xor_sync(0xffffffffu, r, 2);
            inv[mi][rr] = 1.f / r;
        }
    if (qd == 0) {
#pragma unroll
        for (int mi = 0; mi < 2; mi++)
#pragma unroll
            for (int rr = 0; rr < 2; rr++)
                g_invl[hm * LQ + wm + mi * 16 + gr + rr * 8] = inv[mi][rr];
    }
#pragma unroll
    for (int mi = 0; mi < 2; mi++)
#pragma unroll
        for (int ni = 0; ni < 8; ni++)
#pragma unroll
            for (int rr = 0; rr < 2; rr++) {
                int r = wm + mi * 16 + gr + rr * 8;
                int d = ni * 8 + qd * 2;
                *(float2*)&g_z1[(hm * LQ + r) * DHH + d] =
                    make_float2(accz[mi][ni][rr * 2 + 0] * inv[mi][rr],
                                accz[mi][ni][rr * 2 + 1] * inv[mi][rr]);
            }
}

// ============================================================================
// K4: z2 GEMM, 2-stage double buffer (A + KV both), invl applied in reduction
// stage: Ahi(36864) | Alo(36864) | KVhi(9216) | KVlo(9216) = 92160
// ============================================================================
#define Z2_ASZ  (256 * 144)          // 36864
#define Z2_KVSZ (64 * 144)           // 9216
#define Z2_STG  (2 * Z2_ASZ + 2 * Z2_KVSZ)   // 92160
#define Z2_LINV (2 * Z2_STG)                 // 184320
#define Z2_TOT  (Z2_LINV + 1024)             // 185344

__global__ __launch_bounds__(256) void z2_mma_kernel()
{
    extern __shared__ __align__(16) unsigned char dsm[];
    const uint32_t sb = smem_to_u32(dsm);
    const int tid = threadIdx.x, lane = tid & 31, wid = tid >> 5;
    const int hm0 = blockIdx.x * 256;
    const int i = blockIdx.y;
    const int wm = wid * 32;
    float* linv = (float*)(dsm + Z2_LINV);

    linv[tid] = g_invl[(hm0 + tid) * LQ + i];

    auto load_chunk = [&](int jc, int st) {
        uint32_t s0 = sb + st * Z2_STG;
#pragma unroll
        for (int l = 0; l < 8; l++) {
            int id = tid + l * 256;
            int r = id >> 3, c = id & 7;
            int ga = (i * NSL + hm0 + r) * LQ + jc * 64 + c * 8;
            cp16(s0 + r * 144 + c * 16, &g_ahi[ga]);
            cp16(s0 + Z2_ASZ + r * 144 + c * 16, &g_alo[ga]);
        }
#pragma unroll
        for (int l = 0; l < 2; l++) {
            int id = tid + l * 256;
            int r = id >> 3, c = id & 7;
            int gb = (i * LQ + jc * 64 + r) * DHH + c * 8;
            cp16(s0 + 2 * Z2_ASZ + r * 144 + c * 16, &g_avhi[gb]);
            cp16(s0 + 2 * Z2_ASZ + Z2_KVSZ + r * 144 + c * 16, &g_avlo[gb]);
        }
    };

    load_chunk(0, 0);
    CP_COMMIT();

    float acc[2][8][4];
#pragma unroll
    for (int a = 0; a < 2; a++)
#pragma unroll
        for (int b = 0; b < 8; b++)
#pragma unroll
            for (int c = 0; c < 4; c++) acc[a][b][c] = 0.f;

    for (int jc = 0; jc < 4; jc++) {
        const int st = jc & 1;
        __syncthreads();
        if (jc < 3) { load_chunk(jc + 1, st ^ 1); CP_COMMIT(); CP_WAIT(1); }
        else        { CP_WAIT(0); }
        __syncthreads();

        const uint32_t s0 = sb + st * Z2_STG;
#pragma unroll
        for (int s = 0; s < 4; s++) {
            uint32_t ah[2][4], al[2][4];
#pragma unroll
            for (int mi = 0; mi < 2; mi++) {
                uint32_t ad = s0 + (wm + mi * 16 + (lane & 15)) * 144 +
                              s * 32 + ((lane >> 4) & 1) * 16;
                ldsm_x4(ad, ah[mi]);
                ldsm_x4(ad + Z2_ASZ, al[mi]);
            }
#pragma unroll
            for (int p = 0; p < 4; p++) {
                uint32_t bh[4], bl[4];
                uint32_t bd = s0 + 2 * Z2_ASZ + (s * 16 + (lane & 15)) * 144 +
                              p * 32 + ((lane >> 4) & 1) * 16;
                ldsm_x4_t(bd, bh);
                ldsm_x4_t(bd + Z2_KVSZ, bl);
#pragma unroll
                for (int mi = 0; mi < 2; mi++)
#pragma unroll
                    for (int su = 0; su < 2; su++) {
                        mma_bf16(acc[mi][p * 2 + su], ah[mi], &bh[su * 2]);
                        mma_bf16(acc[mi][p * 2 + su], ah[mi], &bl[su * 2]);
                        mma_bf16(acc[mi][p * 2 + su], al[mi], &bh[su * 2]);
                    }
            }
        }
    }

    // reduce over m with per-row invl scaling
    __syncthreads();
    float* Sf = (float*)dsm;   // [256][65] in stage0 region
#pragma unroll
    for (int mi = 0; mi < 2; mi++)
#pragma unroll
        for (int ni = 0; ni < 8; ni++)
#pragma unroll
            for (int rr = 0; rr < 2; rr++) {
                int r = wm + mi * 16 + (lane >> 2) + rr * 8;
                int c = ni * 8 + (lane & 3) * 2;
                Sf[r * 65 + c]     = acc[mi][ni][rr * 2 + 0];
                Sf[r * 65 + c + 1] = acc[mi][ni][rr * 2 + 1];
            }
    __syncthreads();
    {
        int g = tid >> 6, d = tid & 63;
        float s = 0.f;
#pragma unroll 8
        for (int m = 0; m < 64; m++)
            s += Sf[(g * 64 + m) * 65 + d] * linv[g * 64 + m];
        int h = blockIdx.x * 4 + g;
        g_z2[(i * NH + h) * DHH + d] = s;
    }
}

// =============================================================================
// K5: out
// =============================================================================
__global__ __launch_bounds__(256) void final_kernel(float* __restrict__ out)
{
    int g = blockIdx.x * 256 + threadIdx.x;
    int i = g >> 9;
    int rest = g & 511;
    int h = rest >> 6;
    int d = rest & 63;

    const float* zp = &g_z1[((h * NM) * LQ + i) * DHH + d];
    float s = g_z2[(i * NH + h) * DHH + d];
#pragma unroll 8
    for (int m = 0; m < 64; m++) s += zp[m * (LQ * DHH)];
    out[g] = s;
}

// =============================================================================
extern "C" void kernel_launch(void* const* d_in, const int* in_sizes, int n_in,
                              void* d_out, int out_size)
{
    const float* x  = (const float*)d_in[0];
    const float* Wq = (const float*)d_in[1];
    const float* Wk = (const float*)d_in[2];
    const float* Wv = (const float*)d_in[3];
    const float* aK = (const float*)d_in[4];
    const float* aV = (const float*)d_in[5];
    float* out = (float*)d_out;

    cudaFuncSetAttribute(proj_mma_kernel,
                         cudaFuncAttributeMaxDynamicSharedMemorySize, P_TOT);
    cudaFuncSetAttribute(e2_mma_kernel,
                         cudaFuncAttributeMaxDynamicSharedMemorySize, E2_TOT);
    cudaFuncSetAttribute(attn_mma_kernel,
                         cudaFuncAttributeMaxDynamicSharedMemorySize, A2_TOT);
    cudaFuncSetAttribute(z2_mma_kernel,
                         cudaFuncAttributeMaxDynamicSharedMemorySize, Z2_TOT);

    __nv_bfloat16 *xhi_p, *xlo_p, *whi_p, *wlo_p, *akhi_p, *aklo_p, *avhi_p, *avlo_p;
    cudaGetSymbolAddress((void**)&xhi_p,  g_xhi);
    cudaGetSymbolAddress((void**)&xlo_p,  g_xlo);
    cudaGetSymbolAddress((void**)&whi_p,  g_whi);
    cudaGetSymbolAddress((void**)&wlo_p,  g_wlo);
    cudaGetSymbolAddress((void**)&akhi_p, g_akhi);
    cudaGetSymbolAddress((void**)&aklo_p, g_aklo);
    cudaGetSymbolAddress((void**)&avhi_p, g_avhi);
    cudaGetSymbolAddress((void**)&avlo_p, g_avlo);

    SplitArgs sa;
    sa.src[0] = x;  sa.hi[0] = xhi_p;  sa.lo[0] = xlo_p;
    sa.src[1] = Wq; sa.hi[1] = whi_p;  sa.lo[1] = wlo_p;
    sa.src[2] = Wk; sa.hi[2] = whi_p + DMOD * DMOD; sa.lo[2] = wlo_p + DMOD * DMOD;
    sa.src[3] = Wv; sa.hi[3] = whi_p + 2 * DMOD * DMOD; sa.lo[3] = wlo_p + 2 * DMOD * DMOD;
    sa.src[4] = aK; sa.hi[4] = akhi_p; sa.lo[4] = aklo_p;
    sa.src[5] = aV; sa.hi[5] = avhi_p; sa.lo[5] = avlo_p;
    int nv[6] = {NTOK * DMOD / 4, DMOD * DMOD / 4, DMOD * DMOD / 4,
                 DMOD * DMOD / 4, LQ * LQ * DHH / 4, LQ * LQ * DHH / 4};
    sa.off[0] = 0;
    for (int s = 0; s < 6; s++) sa.off[s + 1] = sa.off[s] + nv[s];

    split_all_kernel<<<4096, 256>>>(sa);

    proj_mma_kernel<<<dim3(NTOK / 128, DMOD / 128, 3), 256, P_TOT>>>();
    e2_mma_kernel<<<dim3(4, 2, LQ), 256, E2_TOT>>>();
    attn_mma_kernel<<<NSL, 256, A2_TOT>>>();
    z2_mma_kernel<<<dim3(2, LQ), 256, Z2_TOT>>>();
    final_kernel<<<512, 256>>>(out);
}

// round 8
// speedup vs baseline: 2.9455x; 1.0736x over previous
#include <cuda_runtime.h>
#include <cuda_bf16.h>
#include <cstdint>
#include <math.h>

#define LQ   256
#define DHH  64
#define NH   8
#define NM   64
#define NSL  (NH*NM)   // 512
#define DMOD 512
#define NTOK (NM*LQ)   // 16384

// ---------------- scratch -------------
__device__ float g_e2[LQ * NSL * LQ];        // [i][hm][j]
__device__ float g_z1[NSL * LQ * DHH];       // [hm][i][d]
__device__ float g_z2[LQ * NH * DHH];        // [i][h][d]
__device__ float g_invl[NSL * LQ];           // [hm][i]

__device__ __nv_bfloat16 g_xhi[NTOK * DMOD];
__device__ __nv_bfloat16 g_xlo[NTOK * DMOD];
__device__ __nv_bfloat16 g_whi[3 * DMOD * DMOD];
__device__ __nv_bfloat16 g_wlo[3 * DMOD * DMOD];
__device__ __nv_bfloat16 g_qhi[NSL * LQ * DHH];
__device__ __nv_bfloat16 g_qlo[NSL * LQ * DHH];
__device__ __nv_bfloat16 g_khi[NSL * LQ * DHH];
__device__ __nv_bfloat16 g_klo[NSL * LQ * DHH];
__device__ __nv_bfloat16 g_vhi[NSL * LQ * DHH];
__device__ __nv_bfloat16 g_vlo[NSL * LQ * DHH];
__device__ __nv_bfloat16 g_akhi[LQ * LQ * DHH];
__device__ __nv_bfloat16 g_aklo[LQ * LQ * DHH];
__device__ __nv_bfloat16 g_avhi[LQ * LQ * DHH];
__device__ __nv_bfloat16 g_avlo[LQ * LQ * DHH];
__device__ __nv_bfloat16 g_ahi[LQ * NSL * LQ];   // unnormalized p hi [i][hm][j]
__device__ __nv_bfloat16 g_alo[LQ * NSL * LQ];

// ========================= helpers ==================================
__device__ __forceinline__ uint32_t smem_to_u32(const void* p) {
    uint32_t a;
    asm("{ .reg .u64 t; cvta.to.shared.u64 t, %1; cvt.u32.u64 %0, t; }"
        : "=r"(a) : "l"(p));
    return a;
}
__device__ __forceinline__ void ldsm_x4(uint32_t addr, uint32_t* r) {
    asm volatile("ldmatrix.sync.aligned.m8n8.x4.shared.b16 {%0,%1,%2,%3}, [%4];"
        : "=r"(r[0]), "=r"(r[1]), "=r"(r[2]), "=r"(r[3]) : "r"(addr));
}
__device__ __forceinline__ void ldsm_x4_t(uint32_t addr, uint32_t* r) {
    asm volatile("ldmatrix.sync.aligned.m8n8.x4.trans.shared.b16 {%0,%1,%2,%3}, [%4];"
        : "=r"(r[0]), "=r"(r[1]), "=r"(r[2]), "=r"(r[3]) : "r"(addr));
}
__device__ __forceinline__ void mma_bf16(float* c, const uint32_t* a,
                                         const uint32_t* b) {
    asm volatile(
        "mma.sync.aligned.m16n8k16.row.col.f32.bf16.bf16.f32 "
        "{%0,%1,%2,%3}, {%4,%5,%6,%7}, {%8,%9}, {%0,%1,%2,%3};"
        : "+f"(c[0]), "+f"(c[1]), "+f"(c[2]), "+f"(c[3])
        : "r"(a[0]), "r"(a[1]), "r"(a[2]), "r"(a[3]), "r"(b[0]), "r"(b[1]));
}
__device__ __forceinline__ uint32_t pack_bf16(float a, float b) {
    __nv_bfloat162 h(__float2bfloat16(a), __float2bfloat16(b));
    return *(uint32_t*)&h;
}
__device__ __forceinline__ void cp16(uint32_t s, const void* g) {
    asm volatile("cp.async.cg.shared.global [%0], [%1], 16;"
                 :: "r"(s), "l"(g) : "memory");
}
#define CP_COMMIT() asm volatile("cp.async.commit_group;" ::: "memory")
#define CP_WAIT(n)  asm volatile("cp.async.wait_group %0;" :: "n"(n) : "memory")

// ============================================================================
// merged split
// ============================================================================
struct SplitArgs {
    const float* src[6];
    __nv_bfloat16* hi[6];
    __nv_bfloat16* lo[6];
    int off[7];
};

__global__ __launch_bounds__(256) void split_all_kernel(SplitArgs a)
{
    int total = a.off[6];
    for (int idx = blockIdx.x * 256 + threadIdx.x; idx < total;
         idx += gridDim.x * 256) {
        int seg = 0;
#pragma unroll
        for (int s = 1; s < 6; s++) if (idx >= a.off[s]) seg = s;
        int li = idx - a.off[seg];
        float4 v = *(const float4*)&a.src[seg][li * 4];
        __nv_bfloat16 h0 = __float2bfloat16(v.x);
        __nv_bfloat16 h1 = __float2bfloat16(v.y);
        __nv_bfloat16 h2 = __float2bfloat16(v.z);
        __nv_bfloat16 h3 = __float2bfloat16(v.w);
        __nv_bfloat162 hp0(h0, h1), hp1(h2, h3);
        __nv_bfloat162 lp0(__float2bfloat16(v.x - __bfloat162float(h0)),
                           __float2bfloat16(v.y - __bfloat162float(h1)));
        __nv_bfloat162 lp1(__float2bfloat16(v.z - __bfloat162float(h2)),
                           __float2bfloat16(v.w - __bfloat162float(h3)));
        *(__nv_bfloat162*)&a.hi[seg][li * 4]     = hp0;
        *(__nv_bfloat162*)&a.hi[seg][li * 4 + 2] = hp1;
        *(__nv_bfloat162*)&a.lo[seg][li * 4]     = lp0;
        *(__nv_bfloat162*)&a.lo[seg][li * 4 + 2] = lp1;
    }
}

// ============================================================================
// K1: projection GEMM (unchanged)
// ============================================================================
#define PMAT  (128 * 80)
#define PSTG  (4 * PMAT)
#define P_TOT (2 * PSTG)      // 81920

__global__ __launch_bounds__(256) void proj_mma_kernel()
{
    extern __shared__ __align__(16) unsigned char dsm[];
    const uint32_t sb = smem_to_u32(dsm);

    const int tid = threadIdx.x, lane = tid & 31, wid = tid >> 5;
    const int t0 = blockIdx.x * 128;
    const int n0 = blockIdx.y * 128;
    const int sel = blockIdx.z;

    const __nv_bfloat16* Ah = g_xhi;
    const __nv_bfloat16* Al = g_xlo;
    const __nv_bfloat16* Bh = g_whi + sel * DMOD * DMOD;
    const __nv_bfloat16* Bl = g_wlo + sel * DMOD * DMOD;
    __nv_bfloat16 *hip, *lop;
    if (sel == 0)      { hip = g_qhi; lop = g_qlo; }
    else if (sel == 1) { hip = g_khi; lop = g_klo; }
    else               { hip = g_vhi; lop = g_vlo; }

    const int wm = (wid & 3) * 32;
    const int wn = (wid >> 2) * 64;
    const int lr  = (tid >> 2);
    const int seg = tid & 3;

    auto stage_load = [&](int ch, int st) {
        const int k0 = ch * 32;
        uint32_t s0 = sb + st * PSTG;
#pragma unroll
        for (int l = 0; l < 8; l++) {
            int mat = l >> 1;
            int r = (l & 1) * 64 + lr;
            const __nv_bfloat16* gp;
            int row;
            if (mat == 0)      { gp = Ah; row = t0 + r; }
            else if (mat == 1) { gp = Al; row = t0 + r; }
            else if (mat == 2) { gp = Bh; row = n0 + r; }
            else               { gp = Bl; row = n0 + r; }
            cp16(s0 + mat * PMAT + r * 80 + seg * 16,
                 &gp[row * DMOD + k0 + seg * 8]);
        }
    };

    float acc[2][8][4];
#pragma unroll
    for (int a = 0; a < 2; a++)
#pragma unroll
        for (int b = 0; b < 8; b++)
#pragma unroll
            for (int c = 0; c < 4; c++) acc[a][b][c] = 0.f;

    stage_load(0, 0);
    CP_COMMIT();

    for (int ch = 0; ch < 16; ch++) {
        const int st = ch & 1;
        if (ch + 1 < 16) { stage_load(ch + 1, st ^ 1); CP_COMMIT(); CP_WAIT(1); }
        else             { CP_WAIT(0); }
        __syncthreads();

        const uint32_t s0 = sb + st * PSTG;
#pragma unroll
        for (int s = 0; s < 2; s++) {
            uint32_t ah[2][4], al[2][4];
#pragma unroll
            for (int mi = 0; mi < 2; mi++) {
                int row = wm + mi * 16 + (lane & 15);
                uint32_t ad = s0 + row * 80 + s * 32 + ((lane >> 4) & 1) * 16;
                ldsm_x4(ad, ah[mi]);
                ldsm_x4(ad + PMAT, al[mi]);
            }
#pragma unroll
            for (int p = 0; p < 4; p++) {
                uint32_t bh[4], bl[4];
                int row = wn + p * 16 + (lane & 7) + ((lane >> 4) & 1) * 8;
                uint32_t bd = s0 + 2 * PMAT + row * 80 + s * 32 + ((lane >> 3) & 1) * 16;
                ldsm_x4(bd, bh);
                ldsm_x4(bd + PMAT, bl);
#pragma unroll
                for (int mi = 0; mi < 2; mi++)
#pragma unroll
                    for (int su = 0; su < 2; su++) {
                        mma_bf16(acc[mi][p * 2 + su], ah[mi], &bh[su * 2]);
                        mma_bf16(acc[mi][p * 2 + su], ah[mi], &bl[su * 2]);
                        mma_bf16(acc[mi][p * 2 + su], al[mi], &bh[su * 2]);
                    }
            }
        }
        __syncthreads();
    }

#pragma unroll
    for (int mi = 0; mi < 2; mi++)
#pragma unroll
        for (int ni = 0; ni < 8; ni++) {
            int e = n0 + wn + ni * 8 + (lane & 3) * 2;
            int h = e >> 6, d = e & 63;
#pragma unroll
            for (int rr = 0; rr < 2; rr++) {
                int t = t0 + wm + mi * 16 + (lane >> 2) + rr * 8;
                int m = t >> 8, i = t & 255;
                int idx = ((h * NM + m) * LQ + i) * DHH + d;
                float vx = acc[mi][ni][rr * 2 + 0];
                float vy = acc[mi][ni][rr * 2 + 1];
                __nv_bfloat16 h0 = __float2bfloat16(vx);
                __nv_bfloat16 h1 = __float2bfloat16(vy);
                __nv_bfloat162 hp(h0, h1);
                __nv_bfloat162 lp(__float2bfloat16(vx - __bfloat162float(h0)),
                                  __float2bfloat16(vy - __bfloat162float(h1)));
                *(__nv_bfloat162*)&hip[idx] = hp;
                *(__nv_bfloat162*)&lop[idx] = lp;
            }
        }
}

// ============================================================================
// K2: e2 (unchanged)
// ============================================================================
#define E2_AHI 0
#define E2_ASZ (128 * 144)
#define E2_B   (2 * E2_ASZ)
#define E2_TOT (4 * E2_ASZ)

__global__ __launch_bounds__(256) void e2_mma_kernel()
{
    extern __shared__ __align__(16) unsigned char dsm[];
    const uint32_t sb = smem_to_u32(dsm);

    const int tid = threadIdx.x, lane = tid & 31, wid = tid >> 5;
    const int hm0 = blockIdx.x * 128;
    const int j0  = blockIdx.y * 128;
    const int i   = blockIdx.z;
    const int wm = (wid & 3) * 32;
    const int wn = (wid >> 2) * 64;

#pragma unroll
    for (int l = 0; l < 4; l++) {
        int id = tid + l * 256;
        int r = id >> 3, c = id & 7;
        int ga = ((hm0 + r) * LQ + i) * DHH + c * 8;
        cp16(sb + E2_AHI + r * 144 + c * 16, &g_qhi[ga]);
        cp16(sb + E2_AHI + E2_ASZ + r * 144 + c * 16, &g_qlo[ga]);
        int gb = (i * LQ + j0 + r) * DHH + c * 8;
        cp16(sb + E2_B + r * 144 + c * 16, &g_akhi[gb]);
        cp16(sb + E2_B + E2_ASZ + r * 144 + c * 16, &g_aklo[gb]);
    }
    CP_COMMIT();
    CP_WAIT(0);
    __syncthreads();

    float acc[2][8][4];
#pragma unroll
    for (int a = 0; a < 2; a++)
#pragma unroll
        for (int b = 0; b < 8; b++)
#pragma unroll
            for (int c = 0; c < 4; c++) acc[a][b][c] = 0.f;

#pragma unroll
    for (int s = 0; s < 4; s++) {
        uint32_t ah[2][4], al[2][4];
#pragma unroll
        for (int mi = 0; mi < 2; mi++) {
            uint32_t ad = sb + E2_AHI + (wm + mi * 16 + (lane & 15)) * 144 +
                          s * 32 + ((lane >> 4) & 1) * 16;
            ldsm_x4(ad, ah[mi]);
            ldsm_x4(ad + E2_ASZ, al[mi]);
        }
#pragma unroll
        for (int p = 0; p < 4; p++) {
            uint32_t bh[4], bl[4];
            uint32_t bd = sb + E2_B + (wn + p * 16 + (lane & 7) + ((lane >> 4) & 1) * 8) * 144 +
                          s * 32 + ((lane >> 3) & 1) * 16;
            ldsm_x4(bd, bh);
            ldsm_x4(bd + E2_ASZ, bl);
#pragma unroll
            for (int mi = 0; mi < 2; mi++)
#pragma unroll
                for (int su = 0; su < 2; su++) {
                    mma_bf16(acc[mi][p * 2 + su], ah[mi], &bh[su * 2]);
                    mma_bf16(acc[mi][p * 2 + su], ah[mi], &bl[su * 2]);
                    mma_bf16(acc[mi][p * 2 + su], al[mi], &bh[su * 2]);
                }
        }
    }

#pragma unroll
    for (int mi = 0; mi < 2; mi++)
#pragma unroll
        for (int ni = 0; ni < 8; ni++) {
            int j = j0 + wn + ni * 8 + (lane & 3) * 2;
#pragma unroll
            for (int rr = 0; rr < 2; rr++) {
                int hm = hm0 + wm + mi * 16 + (lane >> 2) + rr * 8;
                *(float2*)&g_e2[(i * NSL + hm) * LQ + j] =
                    make_float2(acc[mi][ni][rr * 2 + 0], acc[mi][ni][rr * 2 + 1]);
            }
        }
}

// ============================================================================
// K3: fused attention; grid (hm, i-half). CTA = 128 q-rows, warp = 16 rows.
// smem: KV stage x2 | Q hi/lo (128 rows)
// ============================================================================
#define A3_KSZ  (64 * 144)           // 9216
#define A3_STG  (4 * A3_KSZ)         // 36864
#define A3_Q    (2 * A3_STG)         // 73728
#define A3_QSZ  (128 * 144)          // 18432
#define A3_TOT  (A3_Q + 2 * A3_QSZ)  // 110592

__global__ __launch_bounds__(256) void attn_mma_kernel()
{
    extern __shared__ __align__(16) unsigned char dsm[];
    const uint32_t sb = smem_to_u32(dsm);
    const int tid = threadIdx.x, lane = tid & 31, wid = tid >> 5;
    const int hm = blockIdx.x;
    const int i0 = blockIdx.y * 128;
    const int wm = wid * 16;
    const int gr = lane >> 2, qd = lane & 3;

    auto load_kv = [&](int jc, int st) {
        uint32_t s0 = sb + st * A3_STG;
#pragma unroll
        for (int l = 0; l < 2; l++) {
            int id = tid + l * 256;
            int r = id >> 3, c = id & 7;
            int gk = (hm * LQ + jc * 64 + r) * DHH + c * 8;
            cp16(s0 + 0 * A3_KSZ + r * 144 + c * 16, &g_khi[gk]);
            cp16(s0 + 1 * A3_KSZ + r * 144 + c * 16, &g_klo[gk]);
            cp16(s0 + 2 * A3_KSZ + r * 144 + c * 16, &g_vhi[gk]);
            cp16(s0 + 3 * A3_KSZ + r * 144 + c * 16, &g_vlo[gk]);
        }
    };

    // Q resident (128 rows)
#pragma unroll
    for (int l = 0; l < 4; l++) {
        int id = tid + l * 256;
        int r = id >> 3, c = id & 7;
        int gq = (hm * LQ + i0 + r) * DHH + c * 8;
        cp16(sb + A3_Q + r * 144 + c * 16, &g_qhi[gq]);
        cp16(sb + A3_Q + A3_QSZ + r * 144 + c * 16, &g_qlo[gq]);
    }
    CP_COMMIT();
    load_kv(0, 0);
    CP_COMMIT();

    float accz[8][4];
#pragma unroll
    for (int b = 0; b < 8; b++)
#pragma unroll
        for (int c = 0; c < 4; c++) accz[b][c] = 0.f;
    float rsum[2] = {0.f, 0.f};

    for (int jc = 0; jc < 4; jc++) {
        const int st = jc & 1;
        __syncthreads();
        if (jc < 3) { load_kv(jc + 1, st ^ 1); CP_COMMIT(); CP_WAIT(1); }
        else        { CP_WAIT(0); }
        __syncthreads();

        const uint32_t s0 = sb + st * A3_STG;

        // ---- scores: e1 = q k^T ----
        float acc[8][4];
#pragma unroll
        for (int b = 0; b < 8; b++)
#pragma unroll
            for (int c = 0; c < 4; c++) acc[b][c] = 0.f;

#pragma unroll
        for (int s = 0; s < 4; s++) {
            uint32_t ah[4], al[4];
            uint32_t ad = sb + A3_Q + (wm + (lane & 15)) * 144 +
                          s * 32 + ((lane >> 4) & 1) * 16;
            ldsm_x4(ad, ah);
            ldsm_x4(ad + A3_QSZ, al);
#pragma unroll
            for (int p = 0; p < 4; p++) {
                uint32_t bh[4], bl[4];
                uint32_t bd = s0 + (p * 16 + (lane & 7) + ((lane >> 4) & 1) * 8) * 144 +
                              s * 32 + ((lane >> 3) & 1) * 16;
                ldsm_x4(bd, bh);
                ldsm_x4(bd + A3_KSZ, bl);
#pragma unroll
                for (int su = 0; su < 2; su++) {
                    mma_bf16(acc[p * 2 + su], ah, &bh[su * 2]);
                    mma_bf16(acc[p * 2 + su], ah, &bl[su * 2]);
                    mma_bf16(acc[p * 2 + su], al, &bh[su * 2]);
                }
            }
        }

        // ---- + e2, scale, exp, rowsum, pack p hi/lo ----
        uint32_t phh[8][2], pll[8][2];
        {
            int ir0 = i0 + wm + gr;
            float2 e2b0[8], e2b1[8];
#pragma unroll
            for (int ni = 0; ni < 8; ni++) {
                int col = jc * 64 + ni * 8 + qd * 2;
                e2b0[ni] = *(const float2*)&g_e2[(ir0 * NSL + hm) * LQ + col];
                e2b1[ni] = *(const float2*)&g_e2[((ir0 + 8) * NSL + hm) * LQ + col];
            }
#pragma unroll
            for (int ni = 0; ni < 8; ni++) {
                int col = jc * 64 + ni * 8 + qd * 2;
                float e0 = __expf((acc[ni][0] + e2b0[ni].x) * 0.125f);
                float e1 = __expf((acc[ni][1] + e2b0[ni].y) * 0.125f);
                float e2v = __expf((acc[ni][2] + e2b1[ni].x) * 0.125f);
                float e3 = __expf((acc[ni][3] + e2b1[ni].y) * 0.125f);
                rsum[0] += e0 + e1;
                rsum[1] += e2v + e3;
                uint32_t h01 = pack_bf16(e0, e1);
                uint32_t h23 = pack_bf16(e2v, e3);
                __nv_bfloat162 hh01 = *(__nv_bfloat162*)&h01;
                __nv_bfloat162 hh23 = *(__nv_bfloat162*)&h23;
                uint32_t l01 = pack_bf16(e0 - __bfloat162float(hh01.x),
                                         e1 - __bfloat162float(hh01.y));
                uint32_t l23 = pack_bf16(e2v - __bfloat162float(hh23.x),
                                         e3 - __bfloat162float(hh23.y));
                phh[ni][0] = h01; phh[ni][1] = h23;
                pll[ni][0] = l01; pll[ni][1] = l23;
                *(uint32_t*)&g_ahi[(ir0 * NSL + hm) * LQ + col] = h01;
                *(uint32_t*)&g_ahi[((ir0 + 8) * NSL + hm) * LQ + col] = h23;
                *(uint32_t*)&g_alo[(ir0 * NSL + hm) * LQ + col] = l01;
                *(uint32_t*)&g_alo[((ir0 + 8) * NSL + hm) * LQ + col] = l23;
            }
        }

        // ---- z1 += p V ----
#pragma unroll
        for (int s = 0; s < 4; s++) {
            uint32_t Ahf[4] = {phh[2 * s][0], phh[2 * s][1],
                               phh[2 * s + 1][0], phh[2 * s + 1][1]};
            uint32_t Alf[4] = {pll[2 * s][0], pll[2 * s][1],
                               pll[2 * s + 1][0], pll[2 * s + 1][1]};
#pragma unroll
            for (int p = 0; p < 4; p++) {
                uint32_t bh[4], bl[4];
                uint32_t bd = s0 + 2 * A3_KSZ + (s * 16 + (lane & 15)) * 144 +
                              p * 32 + ((lane >> 4) & 1) * 16;
                ldsm_x4_t(bd, bh);
                ldsm_x4_t(bd + A3_KSZ, bl);
#pragma unroll
                for (int su = 0; su < 2; su++) {
                    mma_bf16(accz[p * 2 + su], Ahf, &bh[su * 2]);
                    mma_bf16(accz[p * 2 + su], Ahf, &bl[su * 2]);
                    mma_bf16(accz[p * 2 + su], Alf, &bh[su * 2]);
                }
            }
        }
    }

    // ---- finalize ----
    float inv[2];
#pragma unroll
    for (int rr = 0; rr < 2; rr++) {
        float r = rsum[rr];
        r += __shfl_xor_sync(0xffffffffu, r, 1);
        r += __shfl_xor_sync(0xffffffffu, r, 2);
        inv[rr] = 1.f / r;
    }
    if (qd == 0) {
#pragma unroll
        for (int rr = 0; rr < 2; rr++)
            g_invl[hm * LQ + i0 + wm + gr + rr * 8] = inv[rr];
    }
#pragma unroll
    for (int ni = 0; ni < 8; ni++)
#pragma unroll
        for (int rr = 0; rr < 2; rr++) {
            int ir = i0 + wm + gr + rr * 8;
            int d = ni * 8 + qd * 2;
            *(float2*)&g_z1[(hm * LQ + ir) * DHH + d] =
                make_float2(accz[ni][rr * 2 + 0] * inv[rr],
                            accz[ni][rr * 2 + 1] * inv[rr]);
        }
}

// ============================================================================
// K4: z2 GEMM; grid (4 hm-quarters, i). CTA = 128 rows, warp = 16 rows.
// stage: Ahi(18432)|Alo(18432)|KVhi(9216)|KVlo(9216) = 55296, x2 + linv
// ============================================================================
#define Z3_ASZ  (128 * 144)                  // 18432
#define Z3_KVSZ (64 * 144)                   // 9216
#define Z3_STG  (2 * Z3_ASZ + 2 * Z3_KVSZ)   // 55296
#define Z3_LINV (2 * Z3_STG)                 // 110592
#define Z3_TOT  (Z3_LINV + 512)              // 111104

__global__ __launch_bounds__(256) void z2_mma_kernel()
{
    extern __shared__ __align__(16) unsigned char dsm[];
    const uint32_t sb = smem_to_u32(dsm);
    const int tid = threadIdx.x, lane = tid & 31, wid = tid >> 5;
    const int hm0 = blockIdx.x * 128;
    const int i = blockIdx.y;
    const int wm = wid * 16;
    float* linv = (float*)(dsm + Z3_LINV);

    if (tid < 128) linv[tid] = g_invl[(hm0 + tid) * LQ + i];

    auto load_chunk = [&](int jc, int st) {
        uint32_t s0 = sb + st * Z3_STG;
#pragma unroll
        for (int l = 0; l < 4; l++) {
            int id = tid + l * 256;
            int r = id >> 3, c = id & 7;
            int ga = (i * NSL + hm0 + r) * LQ + jc * 64 + c * 8;
            cp16(s0 + r * 144 + c * 16, &g_ahi[ga]);
            cp16(s0 + Z3_ASZ + r * 144 + c * 16, &g_alo[ga]);
        }
#pragma unroll
        for (int l = 0; l < 2; l++) {
            int id = tid + l * 256;
            int r = id >> 3, c = id & 7;
            int gb = (i * LQ + jc * 64 + r) * DHH + c * 8;
            cp16(s0 + 2 * Z3_ASZ + r * 144 + c * 16, &g_avhi[gb]);
            cp16(s0 + 2 * Z3_ASZ + Z3_KVSZ + r * 144 + c * 16, &g_avlo[gb]);
        }
    };

    load_chunk(0, 0);
    CP_COMMIT();

    float acc[8][4];
#pragma unroll
    for (int b = 0; b < 8; b++)
#pragma unroll
        for (int c = 0; c < 4; c++) acc[b][c] = 0.f;

    for (int jc = 0; jc < 4; jc++) {
        const int st = jc & 1;
        __syncthreads();
        if (jc < 3) { load_chunk(jc + 1, st ^ 1); CP_COMMIT(); CP_WAIT(1); }
        else        { CP_WAIT(0); }
        __syncthreads();

        const uint32_t s0 = sb + st * Z3_STG;
#pragma unroll
        for (int s = 0; s < 4; s++) {
            uint32_t ah[4], al[4];
            uint32_t ad = s0 + (wm + (lane & 15)) * 144 +
                          s * 32 + ((lane >> 4) & 1) * 16;
            ldsm_x4(ad, ah);
            ldsm_x4(ad + Z3_ASZ, al);
#pragma unroll
            for (int p = 0; p < 4; p++) {
                uint32_t bh[4], bl[4];
                uint32_t bd = s0 + 2 * Z3_ASZ + (s * 16 + (lane & 15)) * 144 +
                              p * 32 + ((lane >> 4) & 1) * 16;
                ldsm_x4_t(bd, bh);
                ldsm_x4_t(bd + Z3_KVSZ, bl);
#pragma unroll
                for (int su = 0; su < 2; su++) {
                    mma_bf16(acc[p * 2 + su], ah, &bh[su * 2]);
                    mma_bf16(acc[p * 2 + su], ah, &bl[su * 2]);
                    mma_bf16(acc[p * 2 + su], al, &bh[su * 2]);
                }
            }
        }
    }

    // reduce over m (2 h-groups of 64) with invl scaling
    __syncthreads();
    float* Sf = (float*)dsm;   // [128][65]
#pragma unroll
    for (int ni = 0; ni < 8; ni++)
#pragma unroll
        for (int rr = 0; rr < 2; rr++) {
            int r = wm + (lane >> 2) + rr * 8;
            int c = ni * 8 + (lane & 3) * 2;
            Sf[r * 65 + c]     = acc[ni][rr * 2 + 0];
            Sf[r * 65 + c + 1] = acc[ni][rr * 2 + 1];
        }
    __syncthreads();
    if (tid < 128) {
        int g = tid >> 6, d = tid & 63;
        float s = 0.f;
#pragma unroll 8
        for (int m = 0; m < 64; m++)
            s += Sf[(g * 64 + m) * 65 + d] * linv[g * 64 + m];
        int h = blockIdx.x * 2 + g;
        g_z2[(i * NH + h) * DHH + d] = s;
    }
}

// =============================================================================
// K5: out
// =============================================================================
__global__ __launch_bounds__(256) void final_kernel(float* __restrict__ out)
{
    int g = blockIdx.x * 256 + threadIdx.x;
    int i = g >> 9;
    int rest = g & 511;
    int h = rest >> 6;
    int d = rest & 63;

    const float* zp = &g_z1[((h * NM) * LQ + i) * DHH + d];
    float s = g_z2[(i * NH + h) * DHH + d];
#pragma unroll 8
    for (int m = 0; m < 64; m++) s += zp[m * (LQ * DHH)];
    out[g] = s;
}

// =============================================================================
extern "C" void kernel_launch(void* const* d_in, const int* in_sizes, int n_in,
                              void* d_out, int out_size)
{
    const float* x  = (const float*)d_in[0];
    const float* Wq = (const float*)d_in[1];
    const float* Wk = (const float*)d_in[2];
    const float* Wv = (const float*)d_in[3];
    const float* aK = (const float*)d_in[4];
    const float* aV = (const float*)d_in[5];
    float* out = (float*)d_out;

    cudaFuncSetAttribute(proj_mma_kernel,
                         cudaFuncAttributeMaxDynamicSharedMemorySize, P_TOT);
    cudaFuncSetAttribute(e2_mma_kernel,
                         cudaFuncAttributeMaxDynamicSharedMemorySize, E2_TOT);
    cudaFuncSetAttribute(attn_mma_kernel,
                         cudaFuncAttributeMaxDynamicSharedMemorySize, A3_TOT);
    cudaFuncSetAttribute(z2_mma_kernel,
                         cudaFuncAttributeMaxDynamicSharedMemorySize, Z3_TOT);

    __nv_bfloat16 *xhi_p, *xlo_p, *whi_p, *wlo_p, *akhi_p, *aklo_p, *avhi_p, *avlo_p;
    cudaGetSymbolAddress((void**)&xhi_p,  g_xhi);
    cudaGetSymbolAddress((void**)&xlo_p,  g_xlo);
    cudaGetSymbolAddress((void**)&whi_p,  g_whi);
    cudaGetSymbolAddress((void**)&wlo_p,  g_wlo);
    cudaGetSymbolAddress((void**)&akhi_p, g_akhi);
    cudaGetSymbolAddress((void**)&aklo_p, g_aklo);
    cudaGetSymbolAddress((void**)&avhi_p, g_avhi);
    cudaGetSymbolAddress((void**)&avlo_p, g_avlo);

    SplitArgs sa;
    sa.src[0] = x;  sa.hi[0] = xhi_p;  sa.lo[0] = xlo_p;
    sa.src[1] = Wq; sa.hi[1] = whi_p;  sa.lo[1] = wlo_p;
    sa.src[2] = Wk; sa.hi[2] = whi_p + DMOD * DMOD; sa.lo[2] = wlo_p + DMOD * DMOD;
    sa.src[3] = Wv; sa.hi[3] = whi_p + 2 * DMOD * DMOD; sa.lo[3] = wlo_p + 2 * DMOD * DMOD;
    sa.src[4] = aK; sa.hi[4] = akhi_p; sa.lo[4] = aklo_p;
    sa.src[5] = aV; sa.hi[5] = avhi_p; sa.lo[5] = avlo_p;
    int nv[6] = {NTOK * DMOD / 4, DMOD * DMOD / 4, DMOD * DMOD / 4,
                 DMOD * DMOD / 4, LQ * LQ * DHH / 4, LQ * LQ * DHH / 4};
    sa.off[0] = 0;
    for (int s = 0; s < 6; s++) sa.off[s + 1] = sa.off[s] + nv[s];

    split_all_kernel<<<4096, 256>>>(sa);

    proj_mma_kernel<<<dim3(NTOK / 128, DMOD / 128, 3), 256, P_TOT>>>();
    e2_mma_kernel<<<dim3(4, 2, LQ), 256, E2_TOT>>>();
    attn_mma_kernel<<<dim3(NSL, 2), 256, A3_TOT>>>();
    z2_mma_kernel<<<dim3(4, LQ), 256, Z3_TOT>>>();
    final_kernel<<<512, 256>>>(out);
}